// round 8
// baseline (speedup 1.0000x reference)
#include <cuda_runtime.h>
#include <cuda_bf16.h>
#include <math.h>
#include <stdint.h>

// Problem constants
#define B 4
#define C 192
#define C3 576
#define NH 4
#define CPH 48
#define HW 65536
#define IMG 256
#define DW_ROWS 32

// ---------------- device scratch ----------------
__device__ float g_qkv[(size_t)B * C3 * HW];
__device__ __nv_bfloat16 g_dw_hi[(size_t)B * C3 * HW];
__device__ __nv_bfloat16 g_dw_lo[(size_t)B * C3 * HW];
__device__ __nv_bfloat16 g_w_hi[C3 * C];
__device__ __nv_bfloat16 g_w_lo[C3 * C];
__device__ __nv_bfloat16 g_M_hi[B * C * C];
__device__ __nv_bfloat16 g_M_lo[B * C * C];
__device__ float g_ssq_part[B * 2 * C * (IMG / DW_ROWS)];
__device__ float g_sumsq[2][B * C];
__device__ float g_gram_part[(size_t)B * NH * 64 * CPH * CPH];
__device__ float g_gram[B * NH * CPH * CPH];
__device__ float g_attn[B * NH * CPH * CPH];

union BF4 { __nv_bfloat16 h[4]; uint2 u; };

// ---------------- fp32 -> bf16 hi/lo split (weights only) ----------------
__global__ void k_cvt(const float* __restrict__ src,
                      __nv_bfloat16* __restrict__ hi,
                      __nv_bfloat16* __restrict__ lo, int n4)
{
    int i = blockIdx.x * 256 + threadIdx.x;
    if (i >= n4) return;
    float4 v = ((const float4*)src)[i];
    BF4 hh, ll;
    float vv[4] = {v.x, v.y, v.z, v.w};
    #pragma unroll
    for (int j = 0; j < 4; j++) {
        hh.h[j] = __float2bfloat16_rn(vv[j]);
        ll.h[j] = __float2bfloat16_rn(vv[j] - __bfloat162float(hh.h[j]));
    }
    ((uint2*)hi)[i] = hh.u;
    ((uint2*)lo)[i] = ll.u;
}

// ---------------- HMMA helpers ----------------
__device__ __forceinline__ void ldsm_x4(uint32_t& r0, uint32_t& r1, uint32_t& r2, uint32_t& r3, uint32_t addr) {
    asm volatile("ldmatrix.sync.aligned.m8n8.x4.shared.b16 {%0,%1,%2,%3}, [%4];"
                 : "=r"(r0), "=r"(r1), "=r"(r2), "=r"(r3) : "r"(addr));
}
__device__ __forceinline__ void ldsm_x4t(uint32_t& r0, uint32_t& r1, uint32_t& r2, uint32_t& r3, uint32_t addr) {
    asm volatile("ldmatrix.sync.aligned.m8n8.x4.trans.shared.b16 {%0,%1,%2,%3}, [%4];"
                 : "=r"(r0), "=r"(r1), "=r"(r2), "=r"(r3) : "r"(addr));
}
__device__ __forceinline__ void mma16816(float* d, const uint32_t* a, const uint32_t* b) {
    asm volatile("mma.sync.aligned.m16n8k16.row.col.f32.bf16.bf16.f32 "
                 "{%0,%1,%2,%3}, {%4,%5,%6,%7}, {%8,%9}, {%0,%1,%2,%3};"
                 : "+f"(d[0]), "+f"(d[1]), "+f"(d[2]), "+f"(d[3])
                 : "r"(a[0]), "r"(a[1]), "r"(a[2]), "r"(a[3]), "r"(b[0]), "r"(b[1]));
}
__device__ __forceinline__ void cp16(uint32_t saddr, const void* gptr) {
    asm volatile("cp.async.cg.shared.global [%0], [%1], 16;" :: "r"(saddr), "l"(gptr));
}
__device__ __forceinline__ uint32_t cvta_s(const void* p) {
    return (uint32_t)__cvta_generic_to_shared(p);
}

#define GBM 192
#define GBN 128
#define GBK 32
#define AS_STRIDE 40
#define BS_STRIDE 136

// ===================== GEMM1: fused x conversion =====================
// Grid (m-tiles, n-tiles, b) with m FASTEST so the 3 sibling m-tiles of one
// n-slice are adjacent in launch order -> X slice read from DRAM once, L2 after.
#define G1_AS_STG 15360
#define G1_AS_Z   7680
#define G1_BS_OFF 61440
#define G1_BS_Z   4352
#define G1_BF_OFF 78848
#define G1_BF_STG 4224
#define G1_SMEM   112640

__global__ __launch_bounds__(256) void gemm1_fused(
    const __nv_bfloat16* __restrict__ Ahi, const __nv_bfloat16* __restrict__ Alo,
    const float* __restrict__ X, float* __restrict__ Cc)
{
    extern __shared__ char smraw[];
    __nv_bfloat16* As = (__nv_bfloat16*)smraw;
    __nv_bfloat16* Bs = (__nv_bfloat16*)(smraw + G1_BS_OFF);
    float*         Bf = (float*)(smraw + G1_BF_OFF);

    const int b = blockIdx.z;
    X  += (size_t)b * C * HW;
    Cc += (size_t)b * C3 * HW;

    const int m0 = blockIdx.x * GBM;   // m fastest
    const int n0 = blockIdx.y * GBN;

    const int t    = threadIdx.x;
    const int lane = t & 31;
    const int w    = t >> 5;
    const int wm   = w & 3;
    const int wn   = w >> 2;

    float acc[3][8][4];
    #pragma unroll
    for (int mi = 0; mi < 3; mi++)
        #pragma unroll
        for (int ni = 0; ni < 8; ni++)
            #pragma unroll
            for (int r = 0; r < 4; r++) acc[mi][ni][r] = 0.f;

    auto loadStage = [&](int st, int k0) {
        #pragma unroll
        for (int i = 0; i < 3; i++) {
            int e   = t + i * 256;
            int row = e >> 2;
            int kq  = (e & 3) * 8;
            const size_t gsrc = (size_t)(m0 + row) * 192 + k0 + kq;
            cp16(cvta_s(&As[st * G1_AS_STG + 0 * G1_AS_Z + row * AS_STRIDE + kq]), &Ahi[gsrc]);
            cp16(cvta_s(&As[st * G1_AS_STG + 1 * G1_AS_Z + row * AS_STRIDE + kq]), &Alo[gsrc]);
        }
        #pragma unroll
        for (int i = 0; i < 4; i++) {
            int e   = t + i * 256;
            int kr  = e >> 5;
            int nc4 = (e & 31) * 4;
            cp16(cvta_s(&Bf[st * G1_BF_STG + kr * 132 + nc4]),
                 &X[(size_t)(k0 + kr) * HW + n0 + nc4]);
        }
    };

    loadStage(0, 0);
    asm volatile("cp.async.commit_group;");

    #pragma unroll
    for (int it = 0; it < 6; it++) {
        const int st = it & 1;
        if (it < 5) {
            loadStage(st ^ 1, (it + 1) * GBK);
            asm volatile("cp.async.commit_group;");
            asm volatile("cp.async.wait_group 1;");
        } else {
            asm volatile("cp.async.wait_group 0;");
        }
        __syncthreads();

        #pragma unroll
        for (int i = 0; i < 4; i++) {
            int e   = t + i * 256;
            int kr  = e >> 5;
            int nc4 = (e & 31) * 4;
            float4 v = *(float4*)&Bf[st * G1_BF_STG + kr * 132 + nc4];
            BF4 hh, ll;
            float vv[4] = {v.x, v.y, v.z, v.w};
            #pragma unroll
            for (int j = 0; j < 4; j++) {
                hh.h[j] = __float2bfloat16_rn(vv[j]);
                ll.h[j] = __float2bfloat16_rn(vv[j] - __bfloat162float(hh.h[j]));
            }
            *(uint2*)&Bs[0 * G1_BS_Z + kr * BS_STRIDE + nc4] = hh.u;
            *(uint2*)&Bs[1 * G1_BS_Z + kr * BS_STRIDE + nc4] = ll.u;
        }
        __syncthreads();

        const __nv_bfloat16* Asl = &As[st * G1_AS_STG];

        #pragma unroll
        for (int ks = 0; ks < GBK; ks += 16) {
            uint32_t afrag[2][3][4];
            uint32_t bfrag[2][8][2];
            #pragma unroll
            for (int z = 0; z < 2; z++) {
                #pragma unroll
                for (int mi = 0; mi < 3; mi++) {
                    int row = wm * 48 + mi * 16 + (lane & 15);
                    int col = ks + (lane >> 4) * 8;
                    ldsm_x4(afrag[z][mi][0], afrag[z][mi][1], afrag[z][mi][2], afrag[z][mi][3],
                            cvta_s(&Asl[z * G1_AS_Z + row * AS_STRIDE + col]));
                }
                #pragma unroll
                for (int np = 0; np < 4; np++) {
                    int kr = ks + (lane & 15);
                    int nc = wn * 64 + np * 16 + (lane >> 4) * 8;
                    ldsm_x4t(bfrag[z][2*np][0], bfrag[z][2*np][1],
                             bfrag[z][2*np+1][0], bfrag[z][2*np+1][1],
                             cvta_s(&Bs[z * G1_BS_Z + kr * BS_STRIDE + nc]));
                }
            }
            #pragma unroll
            for (int mi = 0; mi < 3; mi++)
                #pragma unroll
                for (int ni = 0; ni < 8; ni++) {
                    mma16816(acc[mi][ni], afrag[0][mi], bfrag[0][ni]);
                    mma16816(acc[mi][ni], afrag[0][mi], bfrag[1][ni]);
                    mma16816(acc[mi][ni], afrag[1][mi], bfrag[0][ni]);
                }
        }
        __syncthreads();
    }

    #pragma unroll
    for (int mi = 0; mi < 3; mi++)
        #pragma unroll
        for (int ni = 0; ni < 8; ni++) {
            int row = m0 + wm * 48 + mi * 16 + (lane >> 2);
            int col = n0 + wn * 64 + ni * 8 + 2 * (lane & 3);
            *(float2*)&Cc[(size_t)row * HW + col]       = *(float2*)&acc[mi][ni][0];
            *(float2*)&Cc[(size_t)(row + 8) * HW + col] = *(float2*)&acc[mi][ni][2];
        }
}

// ===================== GEMM2: pure bf16 hi/lo (pipelined) =====================
#define AS_Z   (GBM * AS_STRIDE)
#define AS_ST  (2 * AS_Z)
#define BS_Z   (GBK * BS_STRIDE)
#define BS_ST  (2 * BS_Z)
#define BS_BASE (2 * AS_ST)
#define GSMEM_BYTES ((BS_BASE + 2 * BS_ST) * 2)

__global__ __launch_bounds__(256) void gemm_bf16_pipe(
    const __nv_bfloat16* __restrict__ Ahi, const __nv_bfloat16* __restrict__ Alo, size_t aBatch,
    const __nv_bfloat16* __restrict__ Xhi, const __nv_bfloat16* __restrict__ Xlo, size_t xBatch,
    float* __restrict__ Cc, size_t cBatch)
{
    extern __shared__ __nv_bfloat16 smem[];
    const int b = blockIdx.z;
    Ahi += (size_t)b * aBatch;  Alo += (size_t)b * aBatch;
    Xhi += (size_t)b * xBatch;  Xlo += (size_t)b * xBatch;
    Cc  += (size_t)b * cBatch;

    const int n0 = blockIdx.x * GBN;
    const int m0 = blockIdx.y * GBM;

    const int t    = threadIdx.x;
    const int lane = t & 31;
    const int w    = t >> 5;
    const int wm   = w & 3;
    const int wn   = w >> 2;

    float acc[3][8][4];
    #pragma unroll
    for (int mi = 0; mi < 3; mi++)
        #pragma unroll
        for (int ni = 0; ni < 8; ni++)
            #pragma unroll
            for (int r = 0; r < 4; r++) acc[mi][ni][r] = 0.f;

    auto loadStage = [&](int st, int k0) {
        #pragma unroll
        for (int i = 0; i < 3; i++) {
            int e   = t + i * 256;
            int row = e >> 2;
            int kq  = (e & 3) * 8;
            const size_t gsrc = (size_t)(m0 + row) * 192 + k0 + kq;
            cp16(cvta_s(&smem[st * AS_ST + 0 * AS_Z + row * AS_STRIDE + kq]), &Ahi[gsrc]);
            cp16(cvta_s(&smem[st * AS_ST + 1 * AS_Z + row * AS_STRIDE + kq]), &Alo[gsrc]);
        }
        #pragma unroll
        for (int i = 0; i < 2; i++) {
            int e  = t + i * 256;
            int kr = e >> 4;
            int nc = (e & 15) * 8;
            const size_t gsrc = (size_t)(k0 + kr) * HW + n0 + nc;
            cp16(cvta_s(&smem[BS_BASE + st * BS_ST + 0 * BS_Z + kr * BS_STRIDE + nc]), &Xhi[gsrc]);
            cp16(cvta_s(&smem[BS_BASE + st * BS_ST + 1 * BS_Z + kr * BS_STRIDE + nc]), &Xlo[gsrc]);
        }
    };

    loadStage(0, 0);
    asm volatile("cp.async.commit_group;");

    #pragma unroll
    for (int it = 0; it < 6; it++) {
        const int st = it & 1;
        if (it < 5) {
            loadStage(st ^ 1, (it + 1) * GBK);
            asm volatile("cp.async.commit_group;");
            asm volatile("cp.async.wait_group 1;");
        } else {
            asm volatile("cp.async.wait_group 0;");
        }
        __syncthreads();

        const __nv_bfloat16* As = &smem[st * AS_ST];
        const __nv_bfloat16* Bs = &smem[BS_BASE + st * BS_ST];

        #pragma unroll
        for (int ks = 0; ks < GBK; ks += 16) {
            uint32_t afrag[2][3][4];
            uint32_t bfrag[2][8][2];
            #pragma unroll
            for (int z = 0; z < 2; z++) {
                #pragma unroll
                for (int mi = 0; mi < 3; mi++) {
                    int row = wm * 48 + mi * 16 + (lane & 15);
                    int col = ks + (lane >> 4) * 8;
                    ldsm_x4(afrag[z][mi][0], afrag[z][mi][1], afrag[z][mi][2], afrag[z][mi][3],
                            cvta_s(&As[z * AS_Z + row * AS_STRIDE + col]));
                }
                #pragma unroll
                for (int np = 0; np < 4; np++) {
                    int kr = ks + (lane & 15);
                    int nc = wn * 64 + np * 16 + (lane >> 4) * 8;
                    ldsm_x4t(bfrag[z][2*np][0], bfrag[z][2*np][1],
                             bfrag[z][2*np+1][0], bfrag[z][2*np+1][1],
                             cvta_s(&Bs[z * BS_Z + kr * BS_STRIDE + nc]));
                }
            }
            #pragma unroll
            for (int mi = 0; mi < 3; mi++)
                #pragma unroll
                for (int ni = 0; ni < 8; ni++) {
                    mma16816(acc[mi][ni], afrag[0][mi], bfrag[0][ni]);
                    mma16816(acc[mi][ni], afrag[0][mi], bfrag[1][ni]);
                    mma16816(acc[mi][ni], afrag[1][mi], bfrag[0][ni]);
                }
        }
        __syncthreads();
    }

    #pragma unroll
    for (int mi = 0; mi < 3; mi++)
        #pragma unroll
        for (int ni = 0; ni < 8; ni++) {
            int row = m0 + wm * 48 + mi * 16 + (lane >> 2);
            int col = n0 + wn * 64 + ni * 8 + 2 * (lane & 3);
            *(float2*)&Cc[(size_t)row * HW + col]       = *(float2*)&acc[mi][ni][0];
            *(float2*)&Cc[(size_t)(row + 8) * HW + col] = *(float2*)&acc[mi][ni][2];
        }
}

// ---------------- tiled depthwise 3x3 conv + fused sumsq (4 cols/thread) -------
__global__ __launch_bounds__(256) void k_dwconv(const float* __restrict__ w)
{
    const int ch = blockIdx.y;
    const int b  = blockIdx.z;
    const int y0 = blockIdx.x * DW_ROWS;
    const int t  = threadIdx.x;
    const int tx = t & 63;
    const int ty = t >> 6;

    __shared__ float tile[DW_ROWS + 2][264];

    const float w0 = __ldg(&w[ch * 9 + 0]), w1 = __ldg(&w[ch * 9 + 1]), w2 = __ldg(&w[ch * 9 + 2]);
    const float w3 = __ldg(&w[ch * 9 + 3]), w4 = __ldg(&w[ch * 9 + 4]), w5 = __ldg(&w[ch * 9 + 5]);
    const float w6 = __ldg(&w[ch * 9 + 6]), w7 = __ldg(&w[ch * 9 + 7]), w8 = __ldg(&w[ch * 9 + 8]);

    const float* src = g_qkv + ((size_t)b * C3 + ch) * HW;

    for (int i = t; i < (DW_ROWS + 2) * 64; i += 256) {
        int r = i >> 6;
        int j = i & 63;
        int y = y0 + r - 1;
        float4 v = make_float4(0.f, 0.f, 0.f, 0.f);
        if (y >= 0 && y < IMG) v = *(const float4*)&src[y * IMG + j * 4];
        *(float4*)&tile[r][4 + 4 * j] = v;
    }
    if (t < DW_ROWS + 2) { tile[t][3] = 0.f; tile[t][260] = 0.f; }
    __syncthreads();

    __nv_bfloat16* hi = g_dw_hi + ((size_t)b * C3 + ch) * HW;
    __nv_bfloat16* lo = g_dw_lo + ((size_t)b * C3 + ch) * HW;

    float r0[6], r1[6], r2[6];
    const int cb = 4 * tx;
    #define LOADROW(dst, R) do {                               \
        float4 mq = *(const float4*)&tile[(R)][4 + cb];        \
        dst[0] = tile[(R)][3 + cb];                            \
        dst[1] = mq.x; dst[2] = mq.y; dst[3] = mq.z; dst[4] = mq.w; \
        dst[5] = tile[(R)][8 + cb];                            \
    } while (0)

    LOADROW(r0, ty * 8 + 0);
    LOADROW(r1, ty * 8 + 1);

    float ssq = 0.f;
    #pragma unroll
    for (int r = 0; r < 8; r++) {
        LOADROW(r2, ty * 8 + r + 2);
        float s[4];
        BF4 hh, ll;
        #pragma unroll
        for (int c = 0; c < 4; c++) {
            s[c] = w0 * r0[c] + w1 * r0[c + 1] + w2 * r0[c + 2]
                 + w3 * r1[c] + w4 * r1[c + 1] + w5 * r1[c + 2]
                 + w6 * r2[c] + w7 * r2[c + 1] + w8 * r2[c + 2];
            hh.h[c] = __float2bfloat16_rn(s[c]);
            ll.h[c] = __float2bfloat16_rn(s[c] - __bfloat162float(hh.h[c]));
            ssq += s[c] * s[c];
        }
        const int p = (y0 + ty * 8 + r) * IMG + cb;
        *(uint2*)&hi[p] = hh.u;
        *(uint2*)&lo[p] = ll.u;
        #pragma unroll
        for (int c = 0; c < 6; c++) { r0[c] = r1[c]; r1[c] = r2[c]; }
    }
    #undef LOADROW

    if (ch < 2 * C) {
        #pragma unroll
        for (int st = 16; st > 0; st >>= 1)
            ssq += __shfl_xor_sync(0xffffffffu, ssq, st);
        __shared__ float wred[8];
        if ((t & 31) == 0) wred[t >> 5] = ssq;
        __syncthreads();
        if (t == 0) {
            float s = 0.f;
            #pragma unroll
            for (int i = 0; i < 8; i++) s += wred[i];
            g_ssq_part[((size_t)b * 2 * C + ch) * (IMG / DW_ROWS) + blockIdx.x] = s;
        }
    }
}

__global__ void k_ssq_reduce()
{
    const int idx = blockIdx.x * blockDim.x + threadIdx.x;
    if (idx >= B * 2 * C) return;
    float s = 0.f;
    #pragma unroll
    for (int i = 0; i < IMG / DW_ROWS; i++)
        s += g_ssq_part[(size_t)idx * (IMG / DW_ROWS) + i];
    const int b  = idx / (2 * C);
    const int ch = idx % (2 * C);
    g_sumsq[ch / C][b * C + ch % C] = s;
}

// ---------------- Gram via HMMA ----------------
__global__ __launch_bounds__(128) void k_gram_mma()
{
    const int chunk = blockIdx.x;
    const int h     = blockIdx.y;
    const int b     = blockIdx.z;

    __shared__ __nv_bfloat16 Qs[2][48][72];
    __shared__ __nv_bfloat16 Ks[2][64][56];

    const size_t qoff = ((size_t)b * C3 + h * CPH) * HW + (size_t)chunk * 2048;
    const __nv_bfloat16* qh = g_dw_hi + qoff;
    const __nv_bfloat16* ql = g_dw_lo + qoff;
    const __nv_bfloat16* kh = qh + (size_t)C * HW;
    const __nv_bfloat16* kl = ql + (size_t)C * HW;

    const int t    = threadIdx.x;
    const int lane = t & 31;
    const int w    = t >> 5;

    float acc[6][4];
    #pragma unroll
    for (int ni = 0; ni < 6; ni++)
        #pragma unroll
        for (int r = 0; r < 4; r++) acc[ni][r] = 0.f;

    for (int it = 0; it < 32; it++) {
        const int px0 = it * 64;
        #pragma unroll
        for (int i = 0; i < 6; i++) {
            int e   = t + i * 128;
            int row = e >> 4;
            int c4  = (e & 15) * 4;
            size_t o = (size_t)row * HW + px0 + c4;
            *(uint2*)&Qs[0][row][c4] = *(const uint2*)&qh[o];
            *(uint2*)&Qs[1][row][c4] = *(const uint2*)&ql[o];
            BF4 vh, vl;
            vh.u = *(const uint2*)&kh[o];
            vl.u = *(const uint2*)&kl[o];
            #pragma unroll
            for (int j = 0; j < 4; j++) {
                Ks[0][c4 + j][row] = vh.h[j];
                Ks[1][c4 + j][row] = vl.h[j];
            }
        }
        __syncthreads();
        if (w < 3) {
            #pragma unroll
            for (int ks = 0; ks < 64; ks += 16) {
                uint32_t afrag[2][4], bfrag[2][6][2];
                #pragma unroll
                for (int z = 0; z < 2; z++) {
                    ldsm_x4(afrag[z][0], afrag[z][1], afrag[z][2], afrag[z][3],
                            cvta_s(&Qs[z][w * 16 + (lane & 15)][ks + (lane >> 4) * 8]));
                    #pragma unroll
                    for (int np = 0; np < 3; np++)
                        ldsm_x4t(bfrag[z][2*np][0], bfrag[z][2*np][1],
                                 bfrag[z][2*np+1][0], bfrag[z][2*np+1][1],
                                 cvta_s(&Ks[z][ks + (lane & 15)][np * 16 + (lane >> 4) * 8]));
                }
                #pragma unroll
                for (int ni = 0; ni < 6; ni++) {
                    mma16816(acc[ni], afrag[0], bfrag[0][ni]);
                    mma16816(acc[ni], afrag[0], bfrag[1][ni]);
                    mma16816(acc[ni], afrag[1], bfrag[0][ni]);
                }
            }
        }
        __syncthreads();
    }

    if (w < 3) {
        const size_t base = (((size_t)(b * NH + h)) * 32 + chunk) * (CPH * CPH);
        #pragma unroll
        for (int ni = 0; ni < 6; ni++) {
            int row = w * 16 + (lane >> 2);
            int col = ni * 8 + 2 * (lane & 3);
            *(float2*)&g_gram_part[base + (size_t)row * CPH + col]       = *(float2*)&acc[ni][0];
            *(float2*)&g_gram_part[base + (size_t)(row + 8) * CPH + col] = *(float2*)&acc[ni][2];
        }
    }
}

__global__ void k_gram_reduce()
{
    const int idx = blockIdx.x * blockDim.x + threadIdx.x;
    if (idx >= B * NH * CPH * CPH) return;
    const int bh = idx / (CPH * CPH);
    const int cd = idx % (CPH * CPH);
    float s = 0.f;
    for (int ck = 0; ck < 32; ck++)
        s += g_gram_part[((size_t)bh * 32 + ck) * (CPH * CPH) + cd];
    g_gram[idx] = s;
}

// ---------------- softmax ----------------
__global__ void k_softmax(const float* __restrict__ temperature)
{
    const int bh = blockIdx.x;
    const int b  = bh >> 2;
    const int h  = bh & 3;
    const int c  = threadIdx.x;
    if (c >= CPH) return;

    const float tv = temperature[h];
    const float nq = fmaxf(sqrtf(g_sumsq[0][b * C + h * CPH + c]), 1e-12f);

    float vals[CPH];
    float mx = -1e30f;
    #pragma unroll 4
    for (int d = 0; d < CPH; d++) {
        float nk = fmaxf(sqrtf(g_sumsq[1][b * C + h * CPH + d]), 1e-12f);
        float v  = g_gram[bh * (CPH * CPH) + c * CPH + d] / (nq * nk) * tv;
        vals[d] = v;
        mx = fmaxf(mx, v);
    }
    float sum = 0.f;
    #pragma unroll 4
    for (int d = 0; d < CPH; d++) {
        vals[d] = expf(vals[d] - mx);
        sum += vals[d];
    }
    const float inv = 1.f / sum;
    #pragma unroll 4
    for (int d = 0; d < CPH; d++)
        g_attn[bh * (CPH * CPH) + c * CPH + d] = vals[d] * inv;
}

// ---------------- M = proj @ blockdiag(attn), fused hi/lo split ----------------
__global__ void k_mixW(const float* __restrict__ proj_w)
{
    const int o  = blockIdx.x;
    const int b  = blockIdx.y;
    const int dg = threadIdx.x;
    const int h  = dg / CPH;
    const int d  = dg % CPH;
    float s = 0.f;
    #pragma unroll 8
    for (int cl = 0; cl < CPH; cl++)
        s += proj_w[o * C + h * CPH + cl] *
             g_attn[((size_t)(b * NH + h)) * (CPH * CPH) + cl * CPH + d];
    __nv_bfloat16 hh = __float2bfloat16_rn(s);
    g_M_hi[((size_t)b * C + o) * C + dg] = hh;
    g_M_lo[((size_t)b * C + o) * C + dg] = __float2bfloat16_rn(s - __bfloat162float(hh));
}

// ---------------- launch ----------------
extern "C" void kernel_launch(void* const* d_in, const int* in_sizes, int n_in,
                              void* d_out, int out_size)
{
    const float* x      = (const float*)d_in[0];
    const float* qkv_w  = (const float*)d_in[1];
    const float* dw_w   = (const float*)d_in[2];
    const float* proj_w = (const float*)d_in[3];
    const float* temp   = (const float*)d_in[4];
    float* out = (float*)d_out;

    float* p_qkv;
    __nv_bfloat16 *p_wh, *p_wl, *p_dh, *p_dl, *p_Mh, *p_Ml;
    cudaGetSymbolAddress((void**)&p_qkv, g_qkv);
    cudaGetSymbolAddress((void**)&p_wh,  g_w_hi);
    cudaGetSymbolAddress((void**)&p_wl,  g_w_lo);
    cudaGetSymbolAddress((void**)&p_dh,  g_dw_hi);
    cudaGetSymbolAddress((void**)&p_dl,  g_dw_lo);
    cudaGetSymbolAddress((void**)&p_Mh,  g_M_hi);
    cudaGetSymbolAddress((void**)&p_Ml,  g_M_lo);

    cudaFuncSetAttribute(gemm1_fused,    cudaFuncAttributeMaxDynamicSharedMemorySize, G1_SMEM);
    cudaFuncSetAttribute(gemm_bf16_pipe, cudaFuncAttributeMaxDynamicSharedMemorySize, GSMEM_BYTES);

    // 0) split weights to bf16 hi/lo (tiny)
    {
        int w4 = C3 * C / 4;
        k_cvt<<<(w4 + 255) / 256, 256>>>(qkv_w, p_wh, p_wl, w4);
    }

    // 1) qkv = W @ x (x converted in-kernel; m fastest for L2 reuse of X)
    gemm1_fused<<<dim3(C3 / GBM, HW / GBN, B), 256, G1_SMEM>>>(p_wh, p_wl, x, p_qkv);

    // 2) depthwise conv + sumsq
    k_dwconv<<<dim3(IMG / DW_ROWS, C3, B), 256>>>(dw_w);
    k_ssq_reduce<<<(B * 2 * C + 255) / 256, 256>>>();

    // 3) Gram (HMMA) + reduce
    k_gram_mma<<<dim3(32, NH, B), 128>>>();
    k_gram_reduce<<<(B * NH * CPH * CPH + 255) / 256, 256>>>();

    // 4) softmax, fold proj into M (hi/lo fused)
    k_softmax<<<B * NH, 64>>>(temp);
    k_mixW<<<dim3(C, B), C>>>(proj_w);

    // 5) out = M @ v
    gemm_bf16_pipe<<<dim3(HW / GBN, C / GBM, B), 256, GSMEM_BYTES>>>(
        p_Mh, p_Ml, (size_t)C * C,
        p_dh + (size_t)2 * C * HW, p_dl + (size_t)2 * C * HW, (size_t)C3 * HW,
        out, (size_t)C * HW);
}

// round 9
// speedup vs baseline: 1.0358x; 1.0358x over previous
#include <cuda_runtime.h>
#include <cuda_bf16.h>
#include <math.h>
#include <stdint.h>

// Problem constants
#define B 4
#define C 192
#define C3 576
#define NH 4
#define CPH 48
#define HW 65536
#define IMG 256
#define DW_ROWS 32

// ---------------- device scratch ----------------
__device__ float g_qkv[(size_t)B * C3 * HW];
__device__ __nv_bfloat16 g_dw_hi[(size_t)B * C3 * HW];
__device__ __nv_bfloat16 g_dw_lo[(size_t)B * C3 * HW];
__device__ __nv_bfloat16 g_w_hi[C3 * C];
__device__ __nv_bfloat16 g_w_lo[C3 * C];
__device__ __nv_bfloat16 g_M_hi[B * C * C];
__device__ __nv_bfloat16 g_M_lo[B * C * C];
__device__ float g_ssq_part[B * 2 * C * (IMG / DW_ROWS)];
__device__ float g_gram_part[(size_t)B * NH * 64 * CPH * CPH];
__device__ float g_gram[B * NH * CPH * CPH];
__device__ float g_attn[B * NH * CPH * CPH];

union BF4 { __nv_bfloat16 h[4]; uint2 u; };

// ---------------- fp32 -> bf16 hi/lo split (weights only) ----------------
__global__ void k_cvt(const float* __restrict__ src,
                      __nv_bfloat16* __restrict__ hi,
                      __nv_bfloat16* __restrict__ lo, int n4)
{
    int i = blockIdx.x * 256 + threadIdx.x;
    if (i >= n4) return;
    float4 v = ((const float4*)src)[i];
    BF4 hh, ll;
    float vv[4] = {v.x, v.y, v.z, v.w};
    #pragma unroll
    for (int j = 0; j < 4; j++) {
        hh.h[j] = __float2bfloat16_rn(vv[j]);
        ll.h[j] = __float2bfloat16_rn(vv[j] - __bfloat162float(hh.h[j]));
    }
    ((uint2*)hi)[i] = hh.u;
    ((uint2*)lo)[i] = ll.u;
}

// ---------------- HMMA helpers ----------------
__device__ __forceinline__ void ldsm_x4(uint32_t& r0, uint32_t& r1, uint32_t& r2, uint32_t& r3, uint32_t addr) {
    asm volatile("ldmatrix.sync.aligned.m8n8.x4.shared.b16 {%0,%1,%2,%3}, [%4];"
                 : "=r"(r0), "=r"(r1), "=r"(r2), "=r"(r3) : "r"(addr));
}
__device__ __forceinline__ void ldsm_x4t(uint32_t& r0, uint32_t& r1, uint32_t& r2, uint32_t& r3, uint32_t addr) {
    asm volatile("ldmatrix.sync.aligned.m8n8.x4.trans.shared.b16 {%0,%1,%2,%3}, [%4];"
                 : "=r"(r0), "=r"(r1), "=r"(r2), "=r"(r3) : "r"(addr));
}
__device__ __forceinline__ void mma16816(float* d, const uint32_t* a, const uint32_t* b) {
    asm volatile("mma.sync.aligned.m16n8k16.row.col.f32.bf16.bf16.f32 "
                 "{%0,%1,%2,%3}, {%4,%5,%6,%7}, {%8,%9}, {%0,%1,%2,%3};"
                 : "+f"(d[0]), "+f"(d[1]), "+f"(d[2]), "+f"(d[3])
                 : "r"(a[0]), "r"(a[1]), "r"(a[2]), "r"(a[3]), "r"(b[0]), "r"(b[1]));
}
__device__ __forceinline__ void cp16(uint32_t saddr, const void* gptr) {
    asm volatile("cp.async.cg.shared.global [%0], [%1], 16;" :: "r"(saddr), "l"(gptr));
}
__device__ __forceinline__ uint32_t cvta_s(const void* p) {
    return (uint32_t)__cvta_generic_to_shared(p);
}

#define GBM 192
#define GBN 128
#define GBK 32
#define AS_STRIDE 40
#define BS_STRIDE 136

// ===================== GEMM1: fused x conversion, 3-stage =====================
// smem: As 3 stages x 2z x 192x40 bf16 = 92160B
//       Bs 2z x 32x136 bf16           = 17408B @ 92160
//       Bf 3 stages x 32x132 fp32     = 50688B @ 109568
#define G1_AS_STG 15360   // elems per stage (2z)
#define G1_AS_Z   7680
#define G1_BS_OFF 92160   // bytes
#define G1_BS_Z   4352
#define G1_BF_OFF 109568  // bytes
#define G1_BF_STG 4224    // floats per stage
#define G1_SMEM   160256

__global__ __launch_bounds__(256) void gemm1_fused(
    const __nv_bfloat16* __restrict__ Ahi, const __nv_bfloat16* __restrict__ Alo,
    const float* __restrict__ X, float* __restrict__ Cc)
{
    extern __shared__ char smraw[];
    __nv_bfloat16* As = (__nv_bfloat16*)smraw;
    __nv_bfloat16* Bs = (__nv_bfloat16*)(smraw + G1_BS_OFF);
    float*         Bf = (float*)(smraw + G1_BF_OFF);

    const int b = blockIdx.z;
    X  += (size_t)b * C * HW;
    Cc += (size_t)b * C3 * HW;

    const int n0 = blockIdx.x * GBN;
    const int m0 = blockIdx.y * GBM;

    const int t    = threadIdx.x;
    const int lane = t & 31;
    const int w    = t >> 5;
    const int wm   = w & 3;
    const int wn   = w >> 2;

    float acc[3][8][4];
    #pragma unroll
    for (int mi = 0; mi < 3; mi++)
        #pragma unroll
        for (int ni = 0; ni < 8; ni++)
            #pragma unroll
            for (int r = 0; r < 4; r++) acc[mi][ni][r] = 0.f;

    auto loadStage = [&](int st, int k0) {
        #pragma unroll
        for (int i = 0; i < 3; i++) {
            int e   = t + i * 256;
            int row = e >> 2;
            int kq  = (e & 3) * 8;
            const size_t gsrc = (size_t)(m0 + row) * 192 + k0 + kq;
            cp16(cvta_s(&As[st * G1_AS_STG + 0 * G1_AS_Z + row * AS_STRIDE + kq]), &Ahi[gsrc]);
            cp16(cvta_s(&As[st * G1_AS_STG + 1 * G1_AS_Z + row * AS_STRIDE + kq]), &Alo[gsrc]);
        }
        #pragma unroll
        for (int i = 0; i < 4; i++) {
            int e   = t + i * 256;
            int kr  = e >> 5;
            int nc4 = (e & 31) * 4;
            cp16(cvta_s(&Bf[st * G1_BF_STG + kr * 132 + nc4]),
                 &X[(size_t)(k0 + kr) * HW + n0 + nc4]);
        }
    };

    loadStage(0, 0);
    asm volatile("cp.async.commit_group;");
    loadStage(1, GBK);
    asm volatile("cp.async.commit_group;");

    #pragma unroll
    for (int it = 0; it < 6; it++) {
        const int st = it % 3;
        if (it < 4) {
            loadStage((it + 2) % 3, (it + 2) * GBK);
            asm volatile("cp.async.commit_group;");
            asm volatile("cp.async.wait_group 2;");
        } else if (it == 4) {
            asm volatile("cp.async.wait_group 1;");
        } else {
            asm volatile("cp.async.wait_group 0;");
        }
        __syncthreads();

        // convert fp32 stage -> hi/lo bf16 Bs (single buffer)
        #pragma unroll
        for (int i = 0; i < 4; i++) {
            int e   = t + i * 256;
            int kr  = e >> 5;
            int nc4 = (e & 31) * 4;
            float4 v = *(float4*)&Bf[st * G1_BF_STG + kr * 132 + nc4];
            BF4 hh, ll;
            float vv[4] = {v.x, v.y, v.z, v.w};
            #pragma unroll
            for (int j = 0; j < 4; j++) {
                hh.h[j] = __float2bfloat16_rn(vv[j]);
                ll.h[j] = __float2bfloat16_rn(vv[j] - __bfloat162float(hh.h[j]));
            }
            *(uint2*)&Bs[0 * G1_BS_Z + kr * BS_STRIDE + nc4] = hh.u;
            *(uint2*)&Bs[1 * G1_BS_Z + kr * BS_STRIDE + nc4] = ll.u;
        }
        __syncthreads();

        const __nv_bfloat16* Asl = &As[st * G1_AS_STG];

        #pragma unroll
        for (int ks = 0; ks < GBK; ks += 16) {
            uint32_t afrag[2][3][4];
            uint32_t bfrag[2][8][2];
            #pragma unroll
            for (int z = 0; z < 2; z++) {
                #pragma unroll
                for (int mi = 0; mi < 3; mi++) {
                    int row = wm * 48 + mi * 16 + (lane & 15);
                    int col = ks + (lane >> 4) * 8;
                    ldsm_x4(afrag[z][mi][0], afrag[z][mi][1], afrag[z][mi][2], afrag[z][mi][3],
                            cvta_s(&Asl[z * G1_AS_Z + row * AS_STRIDE + col]));
                }
                #pragma unroll
                for (int np = 0; np < 4; np++) {
                    int kr = ks + (lane & 15);
                    int nc = wn * 64 + np * 16 + (lane >> 4) * 8;
                    ldsm_x4t(bfrag[z][2*np][0], bfrag[z][2*np][1],
                             bfrag[z][2*np+1][0], bfrag[z][2*np+1][1],
                             cvta_s(&Bs[z * G1_BS_Z + kr * BS_STRIDE + nc]));
                }
            }
            #pragma unroll
            for (int mi = 0; mi < 3; mi++)
                #pragma unroll
                for (int ni = 0; ni < 8; ni++) {
                    mma16816(acc[mi][ni], afrag[0][mi], bfrag[0][ni]);
                    mma16816(acc[mi][ni], afrag[0][mi], bfrag[1][ni]);
                    mma16816(acc[mi][ni], afrag[1][mi], bfrag[0][ni]);
                }
        }
        __syncthreads();
    }

    #pragma unroll
    for (int mi = 0; mi < 3; mi++)
        #pragma unroll
        for (int ni = 0; ni < 8; ni++) {
            int row = m0 + wm * 48 + mi * 16 + (lane >> 2);
            int col = n0 + wn * 64 + ni * 8 + 2 * (lane & 3);
            *(float2*)&Cc[(size_t)row * HW + col]       = *(float2*)&acc[mi][ni][0];
            *(float2*)&Cc[(size_t)(row + 8) * HW + col] = *(float2*)&acc[mi][ni][2];
        }
}

// ===================== GEMM2: pure bf16 hi/lo, 3-stage =====================
#define AS_Z   (GBM * AS_STRIDE)     // 7680
#define AS_ST  (2 * AS_Z)            // 15360
#define BS_Z   (GBK * BS_STRIDE)     // 4352
#define BS_ST  (2 * BS_Z)            // 8704
#define BS_BASE (3 * AS_ST)          // 46080 elems
#define GSMEM_BYTES ((BS_BASE + 3 * BS_ST) * 2)   // 144384 bytes

__global__ __launch_bounds__(256) void gemm_bf16_pipe(
    const __nv_bfloat16* __restrict__ Ahi, const __nv_bfloat16* __restrict__ Alo, size_t aBatch,
    const __nv_bfloat16* __restrict__ Xhi, const __nv_bfloat16* __restrict__ Xlo, size_t xBatch,
    float* __restrict__ Cc, size_t cBatch)
{
    extern __shared__ __nv_bfloat16 smem[];
    const int b = blockIdx.z;
    Ahi += (size_t)b * aBatch;  Alo += (size_t)b * aBatch;
    Xhi += (size_t)b * xBatch;  Xlo += (size_t)b * xBatch;
    Cc  += (size_t)b * cBatch;

    const int n0 = blockIdx.x * GBN;
    const int m0 = blockIdx.y * GBM;

    const int t    = threadIdx.x;
    const int lane = t & 31;
    const int w    = t >> 5;
    const int wm   = w & 3;
    const int wn   = w >> 2;

    float acc[3][8][4];
    #pragma unroll
    for (int mi = 0; mi < 3; mi++)
        #pragma unroll
        for (int ni = 0; ni < 8; ni++)
            #pragma unroll
            for (int r = 0; r < 4; r++) acc[mi][ni][r] = 0.f;

    auto loadStage = [&](int st, int k0) {
        #pragma unroll
        for (int i = 0; i < 3; i++) {
            int e   = t + i * 256;
            int row = e >> 2;
            int kq  = (e & 3) * 8;
            const size_t gsrc = (size_t)(m0 + row) * 192 + k0 + kq;
            cp16(cvta_s(&smem[st * AS_ST + 0 * AS_Z + row * AS_STRIDE + kq]), &Ahi[gsrc]);
            cp16(cvta_s(&smem[st * AS_ST + 1 * AS_Z + row * AS_STRIDE + kq]), &Alo[gsrc]);
        }
        #pragma unroll
        for (int i = 0; i < 2; i++) {
            int e  = t + i * 256;
            int kr = e >> 4;
            int nc = (e & 15) * 8;
            const size_t gsrc = (size_t)(k0 + kr) * HW + n0 + nc;
            cp16(cvta_s(&smem[BS_BASE + st * BS_ST + 0 * BS_Z + kr * BS_STRIDE + nc]), &Xhi[gsrc]);
            cp16(cvta_s(&smem[BS_BASE + st * BS_ST + 1 * BS_Z + kr * BS_STRIDE + nc]), &Xlo[gsrc]);
        }
    };

    loadStage(0, 0);
    asm volatile("cp.async.commit_group;");
    loadStage(1, GBK);
    asm volatile("cp.async.commit_group;");

    #pragma unroll
    for (int it = 0; it < 6; it++) {
        const int st = it % 3;
        if (it < 4) {
            loadStage((it + 2) % 3, (it + 2) * GBK);
            asm volatile("cp.async.commit_group;");
            asm volatile("cp.async.wait_group 2;");
        } else if (it == 4) {
            asm volatile("cp.async.wait_group 1;");
        } else {
            asm volatile("cp.async.wait_group 0;");
        }
        __syncthreads();

        const __nv_bfloat16* As = &smem[st * AS_ST];
        const __nv_bfloat16* Bs = &smem[BS_BASE + st * BS_ST];

        #pragma unroll
        for (int ks = 0; ks < GBK; ks += 16) {
            uint32_t afrag[2][3][4];
            uint32_t bfrag[2][8][2];
            #pragma unroll
            for (int z = 0; z < 2; z++) {
                #pragma unroll
                for (int mi = 0; mi < 3; mi++) {
                    int row = wm * 48 + mi * 16 + (lane & 15);
                    int col = ks + (lane >> 4) * 8;
                    ldsm_x4(afrag[z][mi][0], afrag[z][mi][1], afrag[z][mi][2], afrag[z][mi][3],
                            cvta_s(&As[z * AS_Z + row * AS_STRIDE + col]));
                }
                #pragma unroll
                for (int np = 0; np < 4; np++) {
                    int kr = ks + (lane & 15);
                    int nc = wn * 64 + np * 16 + (lane >> 4) * 8;
                    ldsm_x4t(bfrag[z][2*np][0], bfrag[z][2*np][1],
                             bfrag[z][2*np+1][0], bfrag[z][2*np+1][1],
                             cvta_s(&Bs[z * BS_Z + kr * BS_STRIDE + nc]));
                }
            }
            #pragma unroll
            for (int mi = 0; mi < 3; mi++)
                #pragma unroll
                for (int ni = 0; ni < 8; ni++) {
                    mma16816(acc[mi][ni], afrag[0][mi], bfrag[0][ni]);
                    mma16816(acc[mi][ni], afrag[0][mi], bfrag[1][ni]);
                    mma16816(acc[mi][ni], afrag[1][mi], bfrag[0][ni]);
                }
        }
        __syncthreads();
    }

    #pragma unroll
    for (int mi = 0; mi < 3; mi++)
        #pragma unroll
        for (int ni = 0; ni < 8; ni++) {
            int row = m0 + wm * 48 + mi * 16 + (lane >> 2);
            int col = n0 + wn * 64 + ni * 8 + 2 * (lane & 3);
            *(float2*)&Cc[(size_t)row * HW + col]       = *(float2*)&acc[mi][ni][0];
            *(float2*)&Cc[(size_t)(row + 8) * HW + col] = *(float2*)&acc[mi][ni][2];
        }
}

// ---------------- tiled depthwise 3x3 conv + fused sumsq (4 cols/thread) -------
__global__ __launch_bounds__(256) void k_dwconv(const float* __restrict__ w)
{
    const int ch = blockIdx.y;
    const int b  = blockIdx.z;
    const int y0 = blockIdx.x * DW_ROWS;
    const int t  = threadIdx.x;
    const int tx = t & 63;
    const int ty = t >> 6;

    __shared__ float tile[DW_ROWS + 2][264];

    const float w0 = __ldg(&w[ch * 9 + 0]), w1 = __ldg(&w[ch * 9 + 1]), w2 = __ldg(&w[ch * 9 + 2]);
    const float w3 = __ldg(&w[ch * 9 + 3]), w4 = __ldg(&w[ch * 9 + 4]), w5 = __ldg(&w[ch * 9 + 5]);
    const float w6 = __ldg(&w[ch * 9 + 6]), w7 = __ldg(&w[ch * 9 + 7]), w8 = __ldg(&w[ch * 9 + 8]);

    const float* src = g_qkv + ((size_t)b * C3 + ch) * HW;

    for (int i = t; i < (DW_ROWS + 2) * 64; i += 256) {
        int r = i >> 6;
        int j = i & 63;
        int y = y0 + r - 1;
        float4 v = make_float4(0.f, 0.f, 0.f, 0.f);
        if (y >= 0 && y < IMG) v = *(const float4*)&src[y * IMG + j * 4];
        *(float4*)&tile[r][4 + 4 * j] = v;
    }
    if (t < DW_ROWS + 2) { tile[t][3] = 0.f; tile[t][260] = 0.f; }
    __syncthreads();

    __nv_bfloat16* hi = g_dw_hi + ((size_t)b * C3 + ch) * HW;
    __nv_bfloat16* lo = g_dw_lo + ((size_t)b * C3 + ch) * HW;

    float r0[6], r1[6], r2[6];
    const int cb = 4 * tx;
    #define LOADROW(dst, R) do {                               \
        float4 mq = *(const float4*)&tile[(R)][4 + cb];        \
        dst[0] = tile[(R)][3 + cb];                            \
        dst[1] = mq.x; dst[2] = mq.y; dst[3] = mq.z; dst[4] = mq.w; \
        dst[5] = tile[(R)][8 + cb];                            \
    } while (0)

    LOADROW(r0, ty * 8 + 0);
    LOADROW(r1, ty * 8 + 1);

    float ssq = 0.f;
    #pragma unroll
    for (int r = 0; r < 8; r++) {
        LOADROW(r2, ty * 8 + r + 2);
        float s[4];
        BF4 hh, ll;
        #pragma unroll
        for (int c = 0; c < 4; c++) {
            s[c] = w0 * r0[c] + w1 * r0[c + 1] + w2 * r0[c + 2]
                 + w3 * r1[c] + w4 * r1[c + 1] + w5 * r1[c + 2]
                 + w6 * r2[c] + w7 * r2[c + 1] + w8 * r2[c + 2];
            hh.h[c] = __float2bfloat16_rn(s[c]);
            ll.h[c] = __float2bfloat16_rn(s[c] - __bfloat162float(hh.h[c]));
            ssq += s[c] * s[c];
        }
        const int p = (y0 + ty * 8 + r) * IMG + cb;
        *(uint2*)&hi[p] = hh.u;
        *(uint2*)&lo[p] = ll.u;
        #pragma unroll
        for (int c = 0; c < 6; c++) { r0[c] = r1[c]; r1[c] = r2[c]; }
    }
    #undef LOADROW

    if (ch < 2 * C) {
        #pragma unroll
        for (int st = 16; st > 0; st >>= 1)
            ssq += __shfl_xor_sync(0xffffffffu, ssq, st);
        __shared__ float wred[8];
        if ((t & 31) == 0) wred[t >> 5] = ssq;
        __syncthreads();
        if (t == 0) {
            float s = 0.f;
            #pragma unroll
            for (int i = 0; i < 8; i++) s += wred[i];
            g_ssq_part[((size_t)b * 2 * C + ch) * (IMG / DW_ROWS) + blockIdx.x] = s;
        }
    }
}

// ---------------- Gram via HMMA ----------------
__global__ __launch_bounds__(128) void k_gram_mma()
{
    const int chunk = blockIdx.x;
    const int h     = blockIdx.y;
    const int b     = blockIdx.z;

    __shared__ __nv_bfloat16 Qs[2][48][72];
    __shared__ __nv_bfloat16 Ks[2][64][56];

    const size_t qoff = ((size_t)b * C3 + h * CPH) * HW + (size_t)chunk * 2048;
    const __nv_bfloat16* qh = g_dw_hi + qoff;
    const __nv_bfloat16* ql = g_dw_lo + qoff;
    const __nv_bfloat16* kh = qh + (size_t)C * HW;
    const __nv_bfloat16* kl = ql + (size_t)C * HW;

    const int t    = threadIdx.x;
    const int lane = t & 31;
    const int w    = t >> 5;

    float acc[6][4];
    #pragma unroll
    for (int ni = 0; ni < 6; ni++)
        #pragma unroll
        for (int r = 0; r < 4; r++) acc[ni][r] = 0.f;

    for (int it = 0; it < 32; it++) {
        const int px0 = it * 64;
        #pragma unroll
        for (int i = 0; i < 6; i++) {
            int e   = t + i * 128;
            int row = e >> 4;
            int c4  = (e & 15) * 4;
            size_t o = (size_t)row * HW + px0 + c4;
            *(uint2*)&Qs[0][row][c4] = *(const uint2*)&qh[o];
            *(uint2*)&Qs[1][row][c4] = *(const uint2*)&ql[o];
            BF4 vh, vl;
            vh.u = *(const uint2*)&kh[o];
            vl.u = *(const uint2*)&kl[o];
            #pragma unroll
            for (int j = 0; j < 4; j++) {
                Ks[0][c4 + j][row] = vh.h[j];
                Ks[1][c4 + j][row] = vl.h[j];
            }
        }
        __syncthreads();
        if (w < 3) {
            #pragma unroll
            for (int ks = 0; ks < 64; ks += 16) {
                uint32_t afrag[2][4], bfrag[2][6][2];
                #pragma unroll
                for (int z = 0; z < 2; z++) {
                    ldsm_x4(afrag[z][0], afrag[z][1], afrag[z][2], afrag[z][3],
                            cvta_s(&Qs[z][w * 16 + (lane & 15)][ks + (lane >> 4) * 8]));
                    #pragma unroll
                    for (int np = 0; np < 3; np++)
                        ldsm_x4t(bfrag[z][2*np][0], bfrag[z][2*np][1],
                                 bfrag[z][2*np+1][0], bfrag[z][2*np+1][1],
                                 cvta_s(&Ks[z][ks + (lane & 15)][np * 16 + (lane >> 4) * 8]));
                }
                #pragma unroll
                for (int ni = 0; ni < 6; ni++) {
                    mma16816(acc[ni], afrag[0], bfrag[0][ni]);
                    mma16816(acc[ni], afrag[0], bfrag[1][ni]);
                    mma16816(acc[ni], afrag[1], bfrag[0][ni]);
                }
            }
        }
        __syncthreads();
    }

    if (w < 3) {
        const size_t base = (((size_t)(b * NH + h)) * 32 + chunk) * (CPH * CPH);
        #pragma unroll
        for (int ni = 0; ni < 6; ni++) {
            int row = w * 16 + (lane >> 2);
            int col = ni * 8 + 2 * (lane & 3);
            *(float2*)&g_gram_part[base + (size_t)row * CPH + col]       = *(float2*)&acc[ni][0];
            *(float2*)&g_gram_part[base + (size_t)(row + 8) * CPH + col] = *(float2*)&acc[ni][2];
        }
    }
}

__global__ void k_gram_reduce()
{
    const int idx = blockIdx.x * blockDim.x + threadIdx.x;
    if (idx >= B * NH * CPH * CPH) return;
    const int bh = idx / (CPH * CPH);
    const int cd = idx % (CPH * CPH);
    float s = 0.f;
    for (int ck = 0; ck < 32; ck++)
        s += g_gram_part[((size_t)bh * 32 + ck) * (CPH * CPH) + cd];
    g_gram[idx] = s;
}

// ---------------- softmax (with fused sumsq finalize) ----------------
__global__ void k_softmax(const float* __restrict__ temperature)
{
    const int bh = blockIdx.x;
    const int b  = bh >> 2;
    const int h  = bh & 3;
    const int c  = threadIdx.x;

    __shared__ float snq[CPH], snk[CPH];
    if (c < CPH) {
        float sq = 0.f, sk = 0.f;
        const size_t qb = ((size_t)b * 2 * C + 0 * C + h * CPH + c) * (IMG / DW_ROWS);
        const size_t kb = ((size_t)b * 2 * C + 1 * C + h * CPH + c) * (IMG / DW_ROWS);
        #pragma unroll
        for (int i = 0; i < IMG / DW_ROWS; i++) {
            sq += g_ssq_part[qb + i];
            sk += g_ssq_part[kb + i];
        }
        snq[c] = fmaxf(sqrtf(sq), 1e-12f);
        snk[c] = fmaxf(sqrtf(sk), 1e-12f);
    }
    __syncthreads();
    if (c >= CPH) return;

    const float tv = temperature[h];
    const float nq = snq[c];

    float vals[CPH];
    float mx = -1e30f;
    #pragma unroll 4
    for (int d = 0; d < CPH; d++) {
        float v = g_gram[bh * (CPH * CPH) + c * CPH + d] / (nq * snk[d]) * tv;
        vals[d] = v;
        mx = fmaxf(mx, v);
    }
    float sum = 0.f;
    #pragma unroll 4
    for (int d = 0; d < CPH; d++) {
        vals[d] = expf(vals[d] - mx);
        sum += vals[d];
    }
    const float inv = 1.f / sum;
    #pragma unroll 4
    for (int d = 0; d < CPH; d++)
        g_attn[bh * (CPH * CPH) + c * CPH + d] = vals[d] * inv;
}

// ---------------- M = proj @ blockdiag(attn), fused hi/lo split ----------------
__global__ void k_mixW(const float* __restrict__ proj_w)
{
    const int o  = blockIdx.x;
    const int b  = blockIdx.y;
    const int dg = threadIdx.x;
    const int h  = dg / CPH;
    const int d  = dg % CPH;
    float s = 0.f;
    #pragma unroll 8
    for (int cl = 0; cl < CPH; cl++)
        s += proj_w[o * C + h * CPH + cl] *
             g_attn[((size_t)(b * NH + h)) * (CPH * CPH) + cl * CPH + d];
    __nv_bfloat16 hh = __float2bfloat16_rn(s);
    g_M_hi[((size_t)b * C + o) * C + dg] = hh;
    g_M_lo[((size_t)b * C + o) * C + dg] = __float2bfloat16_rn(s - __bfloat162float(hh));
}

// ---------------- launch ----------------
extern "C" void kernel_launch(void* const* d_in, const int* in_sizes, int n_in,
                              void* d_out, int out_size)
{
    const float* x      = (const float*)d_in[0];
    const float* qkv_w  = (const float*)d_in[1];
    const float* dw_w   = (const float*)d_in[2];
    const float* proj_w = (const float*)d_in[3];
    const float* temp   = (const float*)d_in[4];
    float* out = (float*)d_out;

    float* p_qkv;
    __nv_bfloat16 *p_wh, *p_wl, *p_dh, *p_dl, *p_Mh, *p_Ml;
    cudaGetSymbolAddress((void**)&p_qkv, g_qkv);
    cudaGetSymbolAddress((void**)&p_wh,  g_w_hi);
    cudaGetSymbolAddress((void**)&p_wl,  g_w_lo);
    cudaGetSymbolAddress((void**)&p_dh,  g_dw_hi);
    cudaGetSymbolAddress((void**)&p_dl,  g_dw_lo);
    cudaGetSymbolAddress((void**)&p_Mh,  g_M_hi);
    cudaGetSymbolAddress((void**)&p_Ml,  g_M_lo);

    cudaFuncSetAttribute(gemm1_fused,    cudaFuncAttributeMaxDynamicSharedMemorySize, G1_SMEM);
    cudaFuncSetAttribute(gemm_bf16_pipe, cudaFuncAttributeMaxDynamicSharedMemorySize, GSMEM_BYTES);

    // 0) split weights to bf16 hi/lo (tiny)
    {
        int w4 = C3 * C / 4;
        k_cvt<<<(w4 + 255) / 256, 256>>>(qkv_w, p_wh, p_wl, w4);
    }

    // 1) qkv = W @ x (x converted in-kernel; n-fastest grid, 3-stage pipe)
    gemm1_fused<<<dim3(HW / GBN, C3 / GBM, B), 256, G1_SMEM>>>(p_wh, p_wl, x, p_qkv);

    // 2) depthwise conv + sumsq partials
    k_dwconv<<<dim3(IMG / DW_ROWS, C3, B), 256>>>(dw_w);

    // 3) Gram (HMMA) + reduce
    k_gram_mma<<<dim3(32, NH, B), 128>>>();
    k_gram_reduce<<<(B * NH * CPH * CPH + 255) / 256, 256>>>();

    // 4) softmax (sumsq finalize fused), fold proj into M (hi/lo fused)
    k_softmax<<<B * NH, 64>>>(temp);
    k_mixW<<<dim3(C, B), C>>>(proj_w);

    // 5) out = M @ v (3-stage pipe)
    gemm_bf16_pipe<<<dim3(HW / GBN, C / GBM, B), 256, GSMEM_BYTES>>>(
        p_Mh, p_Ml, (size_t)C * C,
        p_dh + (size_t)2 * C * HW, p_dl + (size_t)2 * C * HW, (size_t)C3 * HW,
        out, (size_t)C * HW);
}

// round 11
// speedup vs baseline: 1.0753x; 1.0382x over previous
#include <cuda_runtime.h>
#include <cuda_bf16.h>
#include <math.h>
#include <stdint.h>

// Problem constants
#define B 4
#define C 192
#define C3 576
#define NH 4
#define CPH 48
#define HW 65536
#define IMG 256
#define DW_ROWS 32

// ---------------- device scratch ----------------
__device__ float g_qkv[(size_t)B * C3 * HW];
__device__ __nv_bfloat16 g_dw_hi[(size_t)B * C3 * HW];
__device__ __nv_bfloat16 g_dw_lo[(size_t)B * C3 * HW];
__device__ __nv_bfloat16 g_w_hi[C3 * C];
__device__ __nv_bfloat16 g_w_lo[C3 * C];
__device__ __nv_bfloat16 g_M_hi[B * C * C];
__device__ __nv_bfloat16 g_M_lo[B * C * C];
__device__ float g_ssq_part[B * 2 * C * (IMG / DW_ROWS)];
__device__ float g_gram_part[(size_t)B * NH * 128 * CPH * CPH];
__device__ float g_gram[B * NH * CPH * CPH];
__device__ float g_attn[B * NH * CPH * CPH];

union BF4 { __nv_bfloat16 h[4]; uint2 u; };

// ---------------- fp32 -> bf16 hi/lo split (weights only) ----------------
__global__ void k_cvt(const float* __restrict__ src,
                      __nv_bfloat16* __restrict__ hi,
                      __nv_bfloat16* __restrict__ lo, int n4)
{
    int i = blockIdx.x * 256 + threadIdx.x;
    if (i >= n4) return;
    float4 v = ((const float4*)src)[i];
    BF4 hh, ll;
    float vv[4] = {v.x, v.y, v.z, v.w};
    #pragma unroll
    for (int j = 0; j < 4; j++) {
        hh.h[j] = __float2bfloat16_rn(vv[j]);
        ll.h[j] = __float2bfloat16_rn(vv[j] - __bfloat162float(hh.h[j]));
    }
    ((uint2*)hi)[i] = hh.u;
    ((uint2*)lo)[i] = ll.u;
}

// ---------------- HMMA helpers ----------------
__device__ __forceinline__ void ldsm_x4(uint32_t& r0, uint32_t& r1, uint32_t& r2, uint32_t& r3, uint32_t addr) {
    asm volatile("ldmatrix.sync.aligned.m8n8.x4.shared.b16 {%0,%1,%2,%3}, [%4];"
                 : "=r"(r0), "=r"(r1), "=r"(r2), "=r"(r3) : "r"(addr));
}
__device__ __forceinline__ void ldsm_x4t(uint32_t& r0, uint32_t& r1, uint32_t& r2, uint32_t& r3, uint32_t addr) {
    asm volatile("ldmatrix.sync.aligned.m8n8.x4.trans.shared.b16 {%0,%1,%2,%3}, [%4];"
                 : "=r"(r0), "=r"(r1), "=r"(r2), "=r"(r3) : "r"(addr));
}
__device__ __forceinline__ void mma16816(float* d, const uint32_t* a, const uint32_t* b) {
    asm volatile("mma.sync.aligned.m16n8k16.row.col.f32.bf16.bf16.f32 "
                 "{%0,%1,%2,%3}, {%4,%5,%6,%7}, {%8,%9}, {%0,%1,%2,%3};"
                 : "+f"(d[0]), "+f"(d[1]), "+f"(d[2]), "+f"(d[3])
                 : "r"(a[0]), "r"(a[1]), "r"(a[2]), "r"(a[3]), "r"(b[0]), "r"(b[1]));
}
__device__ __forceinline__ void mma16816_2(float* d, const uint32_t* a, uint32_t b0, uint32_t b1) {
    asm volatile("mma.sync.aligned.m16n8k16.row.col.f32.bf16.bf16.f32 "
                 "{%0,%1,%2,%3}, {%4,%5,%6,%7}, {%8,%9}, {%0,%1,%2,%3};"
                 : "+f"(d[0]), "+f"(d[1]), "+f"(d[2]), "+f"(d[3])
                 : "r"(a[0]), "r"(a[1]), "r"(a[2]), "r"(a[3]), "r"(b0), "r"(b1));
}
__device__ __forceinline__ void cp16(uint32_t saddr, const void* gptr) {
    asm volatile("cp.async.cg.shared.global [%0], [%1], 16;" :: "r"(saddr), "l"(gptr));
}
__device__ __forceinline__ uint32_t cvta_s(const void* p) {
    return (uint32_t)__cvta_generic_to_shared(p);
}

#define GBM 192
#define GBN 128
#define GBK 32
#define AS_STRIDE 40
#define BS_STRIDE 136

// ===================== GEMM1: fused x conversion, 3-stage =====================
#define G1_AS_STG 15360
#define G1_AS_Z   7680
#define G1_BS_OFF 92160
#define G1_BS_Z   4352
#define G1_BF_OFF 109568
#define G1_BF_STG 4224
#define G1_SMEM   160256

__global__ __launch_bounds__(256) void gemm1_fused(
    const __nv_bfloat16* __restrict__ Ahi, const __nv_bfloat16* __restrict__ Alo,
    const float* __restrict__ X, float* __restrict__ Cc)
{
    extern __shared__ char smraw[];
    __nv_bfloat16* As = (__nv_bfloat16*)smraw;
    __nv_bfloat16* Bs = (__nv_bfloat16*)(smraw + G1_BS_OFF);
    float*         Bf = (float*)(smraw + G1_BF_OFF);

    const int b = blockIdx.z;
    X  += (size_t)b * C * HW;
    Cc += (size_t)b * C3 * HW;

    const int n0 = blockIdx.x * GBN;
    const int m0 = blockIdx.y * GBM;

    const int t    = threadIdx.x;
    const int lane = t & 31;
    const int w    = t >> 5;
    const int wm   = w & 3;
    const int wn   = w >> 2;

    float acc[3][8][4];
    #pragma unroll
    for (int mi = 0; mi < 3; mi++)
        #pragma unroll
        for (int ni = 0; ni < 8; ni++)
            #pragma unroll
            for (int r = 0; r < 4; r++) acc[mi][ni][r] = 0.f;

    auto loadStage = [&](int st, int k0) {
        #pragma unroll
        for (int i = 0; i < 3; i++) {
            int e   = t + i * 256;
            int row = e >> 2;
            int kq  = (e & 3) * 8;
            const size_t gsrc = (size_t)(m0 + row) * 192 + k0 + kq;
            cp16(cvta_s(&As[st * G1_AS_STG + 0 * G1_AS_Z + row * AS_STRIDE + kq]), &Ahi[gsrc]);
            cp16(cvta_s(&As[st * G1_AS_STG + 1 * G1_AS_Z + row * AS_STRIDE + kq]), &Alo[gsrc]);
        }
        #pragma unroll
        for (int i = 0; i < 4; i++) {
            int e   = t + i * 256;
            int kr  = e >> 5;
            int nc4 = (e & 31) * 4;
            cp16(cvta_s(&Bf[st * G1_BF_STG + kr * 132 + nc4]),
                 &X[(size_t)(k0 + kr) * HW + n0 + nc4]);
        }
    };

    loadStage(0, 0);
    asm volatile("cp.async.commit_group;");
    loadStage(1, GBK);
    asm volatile("cp.async.commit_group;");

    #pragma unroll
    for (int it = 0; it < 6; it++) {
        const int st = it % 3;
        if (it < 4) {
            loadStage((it + 2) % 3, (it + 2) * GBK);
            asm volatile("cp.async.commit_group;");
            asm volatile("cp.async.wait_group 2;");
        } else if (it == 4) {
            asm volatile("cp.async.wait_group 1;");
        } else {
            asm volatile("cp.async.wait_group 0;");
        }
        __syncthreads();

        #pragma unroll
        for (int i = 0; i < 4; i++) {
            int e   = t + i * 256;
            int kr  = e >> 5;
            int nc4 = (e & 31) * 4;
            float4 v = *(float4*)&Bf[st * G1_BF_STG + kr * 132 + nc4];
            BF4 hh, ll;
            float vv[4] = {v.x, v.y, v.z, v.w};
            #pragma unroll
            for (int j = 0; j < 4; j++) {
                hh.h[j] = __float2bfloat16_rn(vv[j]);
                ll.h[j] = __float2bfloat16_rn(vv[j] - __bfloat162float(hh.h[j]));
            }
            *(uint2*)&Bs[0 * G1_BS_Z + kr * BS_STRIDE + nc4] = hh.u;
            *(uint2*)&Bs[1 * G1_BS_Z + kr * BS_STRIDE + nc4] = ll.u;
        }
        __syncthreads();

        const __nv_bfloat16* Asl = &As[st * G1_AS_STG];

        #pragma unroll
        for (int ks = 0; ks < GBK; ks += 16) {
            uint32_t afrag[2][3][4];
            uint32_t bfrag[2][8][2];
            #pragma unroll
            for (int z = 0; z < 2; z++) {
                #pragma unroll
                for (int mi = 0; mi < 3; mi++) {
                    int row = wm * 48 + mi * 16 + (lane & 15);
                    int col = ks + (lane >> 4) * 8;
                    ldsm_x4(afrag[z][mi][0], afrag[z][mi][1], afrag[z][mi][2], afrag[z][mi][3],
                            cvta_s(&Asl[z * G1_AS_Z + row * AS_STRIDE + col]));
                }
                #pragma unroll
                for (int np = 0; np < 4; np++) {
                    int kr = ks + (lane & 15);
                    int nc = wn * 64 + np * 16 + (lane >> 4) * 8;
                    ldsm_x4t(bfrag[z][2*np][0], bfrag[z][2*np][1],
                             bfrag[z][2*np+1][0], bfrag[z][2*np+1][1],
                             cvta_s(&Bs[z * G1_BS_Z + kr * BS_STRIDE + nc]));
                }
            }
            #pragma unroll
            for (int mi = 0; mi < 3; mi++)
                #pragma unroll
                for (int ni = 0; ni < 8; ni++) {
                    mma16816(acc[mi][ni], afrag[0][mi], bfrag[0][ni]);
                    mma16816(acc[mi][ni], afrag[0][mi], bfrag[1][ni]);
                    mma16816(acc[mi][ni], afrag[1][mi], bfrag[0][ni]);
                }
        }
        __syncthreads();
    }

    #pragma unroll
    for (int mi = 0; mi < 3; mi++)
        #pragma unroll
        for (int ni = 0; ni < 8; ni++) {
            int row = m0 + wm * 48 + mi * 16 + (lane >> 2);
            int col = n0 + wn * 64 + ni * 8 + 2 * (lane & 3);
            *(float2*)&Cc[(size_t)row * HW + col]       = *(float2*)&acc[mi][ni][0];
            *(float2*)&Cc[(size_t)(row + 8) * HW + col] = *(float2*)&acc[mi][ni][2];
        }
}

// ===================== GEMM2: pure bf16 hi/lo, 3-stage =====================
#define AS_Z   (GBM * AS_STRIDE)
#define AS_ST  (2 * AS_Z)
#define BS_Z   (GBK * BS_STRIDE)
#define BS_ST  (2 * BS_Z)
#define BS_BASE (3 * AS_ST)
#define GSMEM_BYTES ((BS_BASE + 3 * BS_ST) * 2)

__global__ __launch_bounds__(256) void gemm_bf16_pipe(
    const __nv_bfloat16* __restrict__ Ahi, const __nv_bfloat16* __restrict__ Alo, size_t aBatch,
    const __nv_bfloat16* __restrict__ Xhi, const __nv_bfloat16* __restrict__ Xlo, size_t xBatch,
    float* __restrict__ Cc, size_t cBatch)
{
    extern __shared__ __nv_bfloat16 smem[];
    const int b = blockIdx.z;
    Ahi += (size_t)b * aBatch;  Alo += (size_t)b * aBatch;
    Xhi += (size_t)b * xBatch;  Xlo += (size_t)b * xBatch;
    Cc  += (size_t)b * cBatch;

    const int n0 = blockIdx.x * GBN;
    const int m0 = blockIdx.y * GBM;

    const int t    = threadIdx.x;
    const int lane = t & 31;
    const int w    = t >> 5;
    const int wm   = w & 3;
    const int wn   = w >> 2;

    float acc[3][8][4];
    #pragma unroll
    for (int mi = 0; mi < 3; mi++)
        #pragma unroll
        for (int ni = 0; ni < 8; ni++)
            #pragma unroll
            for (int r = 0; r < 4; r++) acc[mi][ni][r] = 0.f;

    auto loadStage = [&](int st, int k0) {
        #pragma unroll
        for (int i = 0; i < 3; i++) {
            int e   = t + i * 256;
            int row = e >> 2;
            int kq  = (e & 3) * 8;
            const size_t gsrc = (size_t)(m0 + row) * 192 + k0 + kq;
            cp16(cvta_s(&smem[st * AS_ST + 0 * AS_Z + row * AS_STRIDE + kq]), &Ahi[gsrc]);
            cp16(cvta_s(&smem[st * AS_ST + 1 * AS_Z + row * AS_STRIDE + kq]), &Alo[gsrc]);
        }
        #pragma unroll
        for (int i = 0; i < 2; i++) {
            int e  = t + i * 256;
            int kr = e >> 4;
            int nc = (e & 15) * 8;
            const size_t gsrc = (size_t)(k0 + kr) * HW + n0 + nc;
            cp16(cvta_s(&smem[BS_BASE + st * BS_ST + 0 * BS_Z + kr * BS_STRIDE + nc]), &Xhi[gsrc]);
            cp16(cvta_s(&smem[BS_BASE + st * BS_ST + 1 * BS_Z + kr * BS_STRIDE + nc]), &Xlo[gsrc]);
        }
    };

    loadStage(0, 0);
    asm volatile("cp.async.commit_group;");
    loadStage(1, GBK);
    asm volatile("cp.async.commit_group;");

    #pragma unroll
    for (int it = 0; it < 6; it++) {
        const int st = it % 3;
        if (it < 4) {
            loadStage((it + 2) % 3, (it + 2) * GBK);
            asm volatile("cp.async.commit_group;");
            asm volatile("cp.async.wait_group 2;");
        } else if (it == 4) {
            asm volatile("cp.async.wait_group 1;");
        } else {
            asm volatile("cp.async.wait_group 0;");
        }
        __syncthreads();

        const __nv_bfloat16* As = &smem[st * AS_ST];
        const __nv_bfloat16* Bs = &smem[BS_BASE + st * BS_ST];

        #pragma unroll
        for (int ks = 0; ks < GBK; ks += 16) {
            uint32_t afrag[2][3][4];
            uint32_t bfrag[2][8][2];
            #pragma unroll
            for (int z = 0; z < 2; z++) {
                #pragma unroll
                for (int mi = 0; mi < 3; mi++) {
                    int row = wm * 48 + mi * 16 + (lane & 15);
                    int col = ks + (lane >> 4) * 8;
                    ldsm_x4(afrag[z][mi][0], afrag[z][mi][1], afrag[z][mi][2], afrag[z][mi][3],
                            cvta_s(&As[z * AS_Z + row * AS_STRIDE + col]));
                }
                #pragma unroll
                for (int np = 0; np < 4; np++) {
                    int kr = ks + (lane & 15);
                    int nc = wn * 64 + np * 16 + (lane >> 4) * 8;
                    ldsm_x4t(bfrag[z][2*np][0], bfrag[z][2*np][1],
                             bfrag[z][2*np+1][0], bfrag[z][2*np+1][1],
                             cvta_s(&Bs[z * BS_Z + kr * BS_STRIDE + nc]));
                }
            }
            #pragma unroll
            for (int mi = 0; mi < 3; mi++)
                #pragma unroll
                for (int ni = 0; ni < 8; ni++) {
                    mma16816(acc[mi][ni], afrag[0][mi], bfrag[0][ni]);
                    mma16816(acc[mi][ni], afrag[0][mi], bfrag[1][ni]);
                    mma16816(acc[mi][ni], afrag[1][mi], bfrag[0][ni]);
                }
        }
        __syncthreads();
    }

    #pragma unroll
    for (int mi = 0; mi < 3; mi++)
        #pragma unroll
        for (int ni = 0; ni < 8; ni++) {
            int row = m0 + wm * 48 + mi * 16 + (lane >> 2);
            int col = n0 + wn * 64 + ni * 8 + 2 * (lane & 3);
            *(float2*)&Cc[(size_t)row * HW + col]       = *(float2*)&acc[mi][ni][0];
            *(float2*)&Cc[(size_t)(row + 8) * HW + col] = *(float2*)&acc[mi][ni][2];
        }
}

// ---------------- tiled depthwise 3x3 conv + fused sumsq (4 cols/thread) -------
__global__ __launch_bounds__(256) void k_dwconv(const float* __restrict__ w)
{
    const int ch = blockIdx.y;
    const int b  = blockIdx.z;
    const int y0 = blockIdx.x * DW_ROWS;
    const int t  = threadIdx.x;
    const int tx = t & 63;
    const int ty = t >> 6;

    __shared__ float tile[DW_ROWS + 2][264];

    const float w0 = __ldg(&w[ch * 9 + 0]), w1 = __ldg(&w[ch * 9 + 1]), w2 = __ldg(&w[ch * 9 + 2]);
    const float w3 = __ldg(&w[ch * 9 + 3]), w4 = __ldg(&w[ch * 9 + 4]), w5 = __ldg(&w[ch * 9 + 5]);
    const float w6 = __ldg(&w[ch * 9 + 6]), w7 = __ldg(&w[ch * 9 + 7]), w8 = __ldg(&w[ch * 9 + 8]);

    const float* src = g_qkv + ((size_t)b * C3 + ch) * HW;

    for (int i = t; i < (DW_ROWS + 2) * 64; i += 256) {
        int r = i >> 6;
        int j = i & 63;
        int y = y0 + r - 1;
        float4 v = make_float4(0.f, 0.f, 0.f, 0.f);
        if (y >= 0 && y < IMG) v = *(const float4*)&src[y * IMG + j * 4];
        *(float4*)&tile[r][4 + 4 * j] = v;
    }
    if (t < DW_ROWS + 2) { tile[t][3] = 0.f; tile[t][260] = 0.f; }
    __syncthreads();

    __nv_bfloat16* hi = g_dw_hi + ((size_t)b * C3 + ch) * HW;
    __nv_bfloat16* lo = g_dw_lo + ((size_t)b * C3 + ch) * HW;

    float r0[6], r1[6], r2[6];
    const int cb = 4 * tx;
    #define LOADROW(dst, R) do {                               \
        float4 mq = *(const float4*)&tile[(R)][4 + cb];        \
        dst[0] = tile[(R)][3 + cb];                            \
        dst[1] = mq.x; dst[2] = mq.y; dst[3] = mq.z; dst[4] = mq.w; \
        dst[5] = tile[(R)][8 + cb];                            \
    } while (0)

    LOADROW(r0, ty * 8 + 0);
    LOADROW(r1, ty * 8 + 1);

    float ssq = 0.f;
    #pragma unroll
    for (int r = 0; r < 8; r++) {
        LOADROW(r2, ty * 8 + r + 2);
        float s[4];
        BF4 hh, ll;
        #pragma unroll
        for (int c = 0; c < 4; c++) {
            s[c] = w0 * r0[c] + w1 * r0[c + 1] + w2 * r0[c + 2]
                 + w3 * r1[c] + w4 * r1[c + 1] + w5 * r1[c + 2]
                 + w6 * r2[c] + w7 * r2[c + 1] + w8 * r2[c + 2];
            hh.h[c] = __float2bfloat16_rn(s[c]);
            ll.h[c] = __float2bfloat16_rn(s[c] - __bfloat162float(hh.h[c]));
            ssq += s[c] * s[c];
        }
        const int p = (y0 + ty * 8 + r) * IMG + cb;
        *(uint2*)&hi[p] = hh.u;
        *(uint2*)&lo[p] = ll.u;
        #pragma unroll
        for (int c = 0; c < 6; c++) { r0[c] = r1[c]; r1[c] = r2[c]; }
    }
    #undef LOADROW

    if (ch < 2 * C) {
        #pragma unroll
        for (int st = 16; st > 0; st >>= 1)
            ssq += __shfl_xor_sync(0xffffffffu, ssq, st);
        __shared__ float wred[8];
        if ((t & 31) == 0) wred[t >> 5] = ssq;
        __syncthreads();
        if (t == 0) {
            float s = 0.f;
            #pragma unroll
            for (int i = 0; i < 8; i++) s += wred[i];
            g_ssq_part[((size_t)b * 2 * C + ch) * (IMG / DW_ROWS) + blockIdx.x] = s;
        }
    }
}

// ---------------- Gram via HMMA, all-warp k-split, no transpose ----------------
// Block 128 threads = 4 warps; each warp owns a 16-px quarter of each 64-px tile
// and accumulates the full 48x48 output. Grid (32, NH, B); 128 split-K partials.
__global__ __launch_bounds__(128) void k_gram_mma()
{
    const int chunk = blockIdx.x;
    const int h     = blockIdx.y;
    const int b     = blockIdx.z;

    __shared__ __nv_bfloat16 Qs[2][48][72];
    __shared__ __nv_bfloat16 Ks[2][48][72];

    const size_t qoff = ((size_t)b * C3 + h * CPH) * HW + (size_t)chunk * 2048;
    const __nv_bfloat16* qh = g_dw_hi + qoff;
    const __nv_bfloat16* ql = g_dw_lo + qoff;
    const __nv_bfloat16* kh = qh + (size_t)C * HW;
    const __nv_bfloat16* kl = ql + (size_t)C * HW;

    const int t    = threadIdx.x;
    const int lane = t & 31;
    const int w    = t >> 5;
    const int ks   = w * 16;       // this warp's k(pixel) quarter

    float acc[3][6][4];
    #pragma unroll
    for (int mi = 0; mi < 3; mi++)
        #pragma unroll
        for (int ni = 0; ni < 6; ni++)
            #pragma unroll
            for (int r = 0; r < 4; r++) acc[mi][ni][r] = 0.f;

    for (int it = 0; it < 32; it++) {
        const int px0 = it * 64;
        #pragma unroll
        for (int i = 0; i < 6; i++) {
            int e   = t + i * 128;       // 0..767
            int row = e >> 4;            // ch 0..47
            int c4  = (e & 15) * 4;      // px 0..60
            size_t o = (size_t)row * HW + px0 + c4;
            *(uint2*)&Qs[0][row][c4] = *(const uint2*)&qh[o];
            *(uint2*)&Qs[1][row][c4] = *(const uint2*)&ql[o];
            *(uint2*)&Ks[0][row][c4] = *(const uint2*)&kh[o];
            *(uint2*)&Ks[1][row][c4] = *(const uint2*)&kl[o];
        }
        __syncthreads();

        uint32_t afrag[2][3][4], bfrag[2][3][4];
        #pragma unroll
        for (int z = 0; z < 2; z++) {
            #pragma unroll
            for (int mi = 0; mi < 3; mi++)
                ldsm_x4(afrag[z][mi][0], afrag[z][mi][1], afrag[z][mi][2], afrag[z][mi][3],
                        cvta_s(&Qs[z][mi * 16 + (lane & 15)][ks + (lane >> 4) * 8]));
            #pragma unroll
            for (int np = 0; np < 3; np++)
                ldsm_x4(bfrag[z][np][0], bfrag[z][np][1], bfrag[z][np][2], bfrag[z][np][3],
                        cvta_s(&Ks[z][np * 16 + (lane & 15)][ks + (lane >> 4) * 8]));
        }
        // B frag pairing from non-trans x4 over [n16][k16]: n-lo={r0,r2}, n-hi={r1,r3}
        #pragma unroll
        for (int mi = 0; mi < 3; mi++)
            #pragma unroll
            for (int np = 0; np < 3; np++) {
                mma16816_2(acc[mi][2*np],   afrag[0][mi], bfrag[0][np][0], bfrag[0][np][2]);
                mma16816_2(acc[mi][2*np],   afrag[0][mi], bfrag[1][np][0], bfrag[1][np][2]);
                mma16816_2(acc[mi][2*np],   afrag[1][mi], bfrag[0][np][0], bfrag[0][np][2]);
                mma16816_2(acc[mi][2*np+1], afrag[0][mi], bfrag[0][np][1], bfrag[0][np][3]);
                mma16816_2(acc[mi][2*np+1], afrag[0][mi], bfrag[1][np][1], bfrag[1][np][3]);
                mma16816_2(acc[mi][2*np+1], afrag[1][mi], bfrag[0][np][1], bfrag[0][np][3]);
            }
        __syncthreads();
    }

    const size_t base = (((size_t)(b * NH + h)) * 128 + chunk * 4 + w) * (CPH * CPH);
    #pragma unroll
    for (int mi = 0; mi < 3; mi++)
        #pragma unroll
        for (int ni = 0; ni < 6; ni++) {
            int row = mi * 16 + (lane >> 2);
            int col = ni * 8 + 2 * (lane & 3);
            *(float2*)&g_gram_part[base + (size_t)row * CPH + col]       = *(float2*)&acc[mi][ni][0];
            *(float2*)&g_gram_part[base + (size_t)(row + 8) * CPH + col] = *(float2*)&acc[mi][ni][2];
        }
}

__global__ void k_gram_reduce()
{
    const int idx = blockIdx.x * blockDim.x + threadIdx.x;
    if (idx >= B * NH * CPH * CPH) return;
    const int bh = idx / (CPH * CPH);
    const int cd = idx % (CPH * CPH);
    float s = 0.f;
    for (int ck = 0; ck < 128; ck++)
        s += g_gram_part[((size_t)bh * 128 + ck) * (CPH * CPH) + cd];
    g_gram[idx] = s;
}

// ---------------- softmax (with fused sumsq finalize) ----------------
__global__ void k_softmax(const float* __restrict__ temperature)
{
    const int bh = blockIdx.x;
    const int b  = bh >> 2;
    const int h  = bh & 3;
    const int c  = threadIdx.x;

    __shared__ float snq[CPH], snk[CPH];
    if (c < CPH) {
        float sq = 0.f, sk = 0.f;
        const size_t qb = ((size_t)b * 2 * C + 0 * C + h * CPH + c) * (IMG / DW_ROWS);
        const size_t kb = ((size_t)b * 2 * C + 1 * C + h * CPH + c) * (IMG / DW_ROWS);
        #pragma unroll
        for (int i = 0; i < IMG / DW_ROWS; i++) {
            sq += g_ssq_part[qb + i];
            sk += g_ssq_part[kb + i];
        }
        snq[c] = fmaxf(sqrtf(sq), 1e-12f);
        snk[c] = fmaxf(sqrtf(sk), 1e-12f);
    }
    __syncthreads();
    if (c >= CPH) return;

    const float tv = temperature[h];
    const float nq = snq[c];

    float vals[CPH];
    float mx = -1e30f;
    #pragma unroll 4
    for (int d = 0; d < CPH; d++) {
        float v = g_gram[bh * (CPH * CPH) + c * CPH + d] / (nq * snk[d]) * tv;
        vals[d] = v;
        mx = fmaxf(mx, v);
    }
    float sum = 0.f;
    #pragma unroll 4
    for (int d = 0; d < CPH; d++) {
        vals[d] = expf(vals[d] - mx);
        sum += vals[d];
    }
    const float inv = 1.f / sum;
    #pragma unroll 4
    for (int d = 0; d < CPH; d++)
        g_attn[bh * (CPH * CPH) + c * CPH + d] = vals[d] * inv;
}

// ---------------- M = proj @ blockdiag(attn), fused hi/lo split ----------------
__global__ void k_mixW(const float* __restrict__ proj_w)
{
    const int o  = blockIdx.x;
    const int b  = blockIdx.y;
    const int dg = threadIdx.x;
    const int h  = dg / CPH;
    const int d  = dg % CPH;
    float s = 0.f;
    #pragma unroll 8
    for (int cl = 0; cl < CPH; cl++)
        s += proj_w[o * C + h * CPH + cl] *
             g_attn[((size_t)(b * NH + h)) * (CPH * CPH) + cl * CPH + d];
    __nv_bfloat16 hh = __float2bfloat16_rn(s);
    g_M_hi[((size_t)b * C + o) * C + dg] = hh;
    g_M_lo[((size_t)b * C + o) * C + dg] = __float2bfloat16_rn(s - __bfloat162float(hh));
}

// ---------------- launch ----------------
extern "C" void kernel_launch(void* const* d_in, const int* in_sizes, int n_in,
                              void* d_out, int out_size)
{
    const float* x      = (const float*)d_in[0];
    const float* qkv_w  = (const float*)d_in[1];
    const float* dw_w   = (const float*)d_in[2];
    const float* proj_w = (const float*)d_in[3];
    const float* temp   = (const float*)d_in[4];
    float* out = (float*)d_out;

    float* p_qkv;
    __nv_bfloat16 *p_wh, *p_wl, *p_dh, *p_dl, *p_Mh, *p_Ml;
    cudaGetSymbolAddress((void**)&p_qkv, g_qkv);
    cudaGetSymbolAddress((void**)&p_wh,  g_w_hi);
    cudaGetSymbolAddress((void**)&p_wl,  g_w_lo);
    cudaGetSymbolAddress((void**)&p_dh,  g_dw_hi);
    cudaGetSymbolAddress((void**)&p_dl,  g_dw_lo);
    cudaGetSymbolAddress((void**)&p_Mh,  g_M_hi);
    cudaGetSymbolAddress((void**)&p_Ml,  g_M_lo);

    cudaFuncSetAttribute(gemm1_fused,    cudaFuncAttributeMaxDynamicSharedMemorySize, G1_SMEM);
    cudaFuncSetAttribute(gemm_bf16_pipe, cudaFuncAttributeMaxDynamicSharedMemorySize, GSMEM_BYTES);

    // 0) split weights to bf16 hi/lo (tiny)
    {
        int w4 = C3 * C / 4;
        k_cvt<<<(w4 + 255) / 256, 256>>>(qkv_w, p_wh, p_wl, w4);
    }

    // 1) qkv = W @ x
    gemm1_fused<<<dim3(HW / GBN, C3 / GBM, B), 256, G1_SMEM>>>(p_wh, p_wl, x, p_qkv);

    // 2) depthwise conv + sumsq partials
    k_dwconv<<<dim3(IMG / DW_ROWS, C3, B), 256>>>(dw_w);

    // 3) Gram (HMMA, all-warp) + reduce
    k_gram_mma<<<dim3(32, NH, B), 128>>>();
    k_gram_reduce<<<(B * NH * CPH * CPH + 255) / 256, 256>>>();

    // 4) softmax (sumsq fused), fold proj into M (hi/lo fused)
    k_softmax<<<B * NH, 64>>>(temp);
    k_mixW<<<dim3(C, B), C>>>(proj_w);

    // 5) out = M @ v
    gemm_bf16_pipe<<<dim3(HW / GBN, C / GBM, B), 256, GSMEM_BYTES>>>(
        p_Mh, p_Ml, (size_t)C * C,
        p_dh + (size_t)2 * C * HW, p_dl + (size_t)2 * C * HW, (size_t)C3 * HW,
        out, (size_t)C * HW);
}

// round 15
// speedup vs baseline: 1.1006x; 1.0235x over previous
#include <cuda_runtime.h>
#include <cuda_bf16.h>
#include <math.h>
#include <stdint.h>

// Problem constants
#define B 4
#define C 192
#define C3 576
#define NH 4
#define CPH 48
#define HW 65536
#define IMG 256
#define DW_ROWS 32

// ---------------- device scratch ----------------
__device__ float g_qkv[(size_t)B * C3 * HW];
__device__ __nv_bfloat16 g_dw_hi[(size_t)B * C3 * HW];
__device__ __nv_bfloat16 g_dw_lo[(size_t)B * C3 * HW];
__device__ __nv_bfloat16 g_w_hi[C3 * C];
__device__ __nv_bfloat16 g_w_lo[C3 * C];
__device__ __nv_bfloat16 g_M_hi[B * C * C];
__device__ __nv_bfloat16 g_M_lo[B * C * C];
__device__ float g_ssq_part[B * 2 * C * (IMG / DW_ROWS)];
__device__ float g_gram_part[(size_t)B * NH * 256 * CPH * CPH];
__device__ float g_gram[B * NH * CPH * CPH];
__device__ float g_attn[B * NH * CPH * CPH];

union BF4 { __nv_bfloat16 h[4]; uint2 u; };

// ---------------- fp32 -> bf16 hi/lo split (weights only) ----------------
__global__ void k_cvt(const float* __restrict__ src,
                      __nv_bfloat16* __restrict__ hi,
                      __nv_bfloat16* __restrict__ lo, int n4)
{
    int i = blockIdx.x * 256 + threadIdx.x;
    if (i >= n4) return;
    float4 v = ((const float4*)src)[i];
    BF4 hh, ll;
    float vv[4] = {v.x, v.y, v.z, v.w};
    #pragma unroll
    for (int j = 0; j < 4; j++) {
        hh.h[j] = __float2bfloat16_rn(vv[j]);
        ll.h[j] = __float2bfloat16_rn(vv[j] - __bfloat162float(hh.h[j]));
    }
    ((uint2*)hi)[i] = hh.u;
    ((uint2*)lo)[i] = ll.u;
}

// ---------------- HMMA helpers ----------------
__device__ __forceinline__ void ldsm_x4(uint32_t& r0, uint32_t& r1, uint32_t& r2, uint32_t& r3, uint32_t addr) {
    asm volatile("ldmatrix.sync.aligned.m8n8.x4.shared.b16 {%0,%1,%2,%3}, [%4];"
                 : "=r"(r0), "=r"(r1), "=r"(r2), "=r"(r3) : "r"(addr));
}
__device__ __forceinline__ void ldsm_x4t(uint32_t& r0, uint32_t& r1, uint32_t& r2, uint32_t& r3, uint32_t addr) {
    asm volatile("ldmatrix.sync.aligned.m8n8.x4.trans.shared.b16 {%0,%1,%2,%3}, [%4];"
                 : "=r"(r0), "=r"(r1), "=r"(r2), "=r"(r3) : "r"(addr));
}
__device__ __forceinline__ void mma16816(float* d, const uint32_t* a, const uint32_t* b) {
    asm volatile("mma.sync.aligned.m16n8k16.row.col.f32.bf16.bf16.f32 "
                 "{%0,%1,%2,%3}, {%4,%5,%6,%7}, {%8,%9}, {%0,%1,%2,%3};"
                 : "+f"(d[0]), "+f"(d[1]), "+f"(d[2]), "+f"(d[3])
                 : "r"(a[0]), "r"(a[1]), "r"(a[2]), "r"(a[3]), "r"(b[0]), "r"(b[1]));
}
__device__ __forceinline__ void mma16816_2(float* d, const uint32_t* a, uint32_t b0, uint32_t b1) {
    asm volatile("mma.sync.aligned.m16n8k16.row.col.f32.bf16.bf16.f32 "
                 "{%0,%1,%2,%3}, {%4,%5,%6,%7}, {%8,%9}, {%0,%1,%2,%3};"
                 : "+f"(d[0]), "+f"(d[1]), "+f"(d[2]), "+f"(d[3])
                 : "r"(a[0]), "r"(a[1]), "r"(a[2]), "r"(a[3]), "r"(b0), "r"(b1));
}
__device__ __forceinline__ void cp16(uint32_t saddr, const void* gptr) {
    asm volatile("cp.async.cg.shared.global [%0], [%1], 16;" :: "r"(saddr), "l"(gptr));
}
__device__ __forceinline__ uint32_t cvta_s(const void* p) {
    return (uint32_t)__cvta_generic_to_shared(p);
}

#define GBM 192
#define GBN 128
#define GBK 32
#define AS_STRIDE 40
#define BS_STRIDE 136

// ===================== GEMM1: fused x conversion, 3-stage =====================
#define G1_AS_STG 15360
#define G1_AS_Z   7680
#define G1_BS_OFF 92160
#define G1_BS_Z   4352
#define G1_BF_OFF 109568
#define G1_BF_STG 4224
#define G1_SMEM   160256

__global__ __launch_bounds__(256) void gemm1_fused(
    const __nv_bfloat16* __restrict__ Ahi, const __nv_bfloat16* __restrict__ Alo,
    const float* __restrict__ X, float* __restrict__ Cc)
{
    extern __shared__ char smraw[];
    __nv_bfloat16* As = (__nv_bfloat16*)smraw;
    __nv_bfloat16* Bs = (__nv_bfloat16*)(smraw + G1_BS_OFF);
    float*         Bf = (float*)(smraw + G1_BF_OFF);

    const int b = blockIdx.z;
    X  += (size_t)b * C * HW;
    Cc += (size_t)b * C3 * HW;

    const int n0 = blockIdx.x * GBN;
    const int m0 = blockIdx.y * GBM;

    const int t    = threadIdx.x;
    const int lane = t & 31;
    const int w    = t >> 5;
    const int wm   = w & 3;
    const int wn   = w >> 2;

    float acc[3][8][4];
    #pragma unroll
    for (int mi = 0; mi < 3; mi++)
        #pragma unroll
        for (int ni = 0; ni < 8; ni++)
            #pragma unroll
            for (int r = 0; r < 4; r++) acc[mi][ni][r] = 0.f;

    auto loadStage = [&](int st, int k0) {
        #pragma unroll
        for (int i = 0; i < 3; i++) {
            int e   = t + i * 256;
            int row = e >> 2;
            int kq  = (e & 3) * 8;
            const size_t gsrc = (size_t)(m0 + row) * 192 + k0 + kq;
            cp16(cvta_s(&As[st * G1_AS_STG + 0 * G1_AS_Z + row * AS_STRIDE + kq]), &Ahi[gsrc]);
            cp16(cvta_s(&As[st * G1_AS_STG + 1 * G1_AS_Z + row * AS_STRIDE + kq]), &Alo[gsrc]);
        }
        #pragma unroll
        for (int i = 0; i < 4; i++) {
            int e   = t + i * 256;
            int kr  = e >> 5;
            int nc4 = (e & 31) * 4;
            cp16(cvta_s(&Bf[st * G1_BF_STG + kr * 132 + nc4]),
                 &X[(size_t)(k0 + kr) * HW + n0 + nc4]);
        }
    };

    loadStage(0, 0);
    asm volatile("cp.async.commit_group;");
    loadStage(1, GBK);
    asm volatile("cp.async.commit_group;");

    #pragma unroll
    for (int it = 0; it < 6; it++) {
        const int st = it % 3;
        if (it < 4) {
            loadStage((it + 2) % 3, (it + 2) * GBK);
            asm volatile("cp.async.commit_group;");
            asm volatile("cp.async.wait_group 2;");
        } else if (it == 4) {
            asm volatile("cp.async.wait_group 1;");
        } else {
            asm volatile("cp.async.wait_group 0;");
        }
        __syncthreads();

        #pragma unroll
        for (int i = 0; i < 4; i++) {
            int e   = t + i * 256;
            int kr  = e >> 5;
            int nc4 = (e & 31) * 4;
            float4 v = *(float4*)&Bf[st * G1_BF_STG + kr * 132 + nc4];
            BF4 hh, ll;
            float vv[4] = {v.x, v.y, v.z, v.w};
            #pragma unroll
            for (int j = 0; j < 4; j++) {
                hh.h[j] = __float2bfloat16_rn(vv[j]);
                ll.h[j] = __float2bfloat16_rn(vv[j] - __bfloat162float(hh.h[j]));
            }
            *(uint2*)&Bs[0 * G1_BS_Z + kr * BS_STRIDE + nc4] = hh.u;
            *(uint2*)&Bs[1 * G1_BS_Z + kr * BS_STRIDE + nc4] = ll.u;
        }
        __syncthreads();

        const __nv_bfloat16* Asl = &As[st * G1_AS_STG];

        #pragma unroll
        for (int ks = 0; ks < GBK; ks += 16) {
            uint32_t afrag[2][3][4];
            uint32_t bfrag[2][8][2];
            #pragma unroll
            for (int z = 0; z < 2; z++) {
                #pragma unroll
                for (int mi = 0; mi < 3; mi++) {
                    int row = wm * 48 + mi * 16 + (lane & 15);
                    int col = ks + (lane >> 4) * 8;
                    ldsm_x4(afrag[z][mi][0], afrag[z][mi][1], afrag[z][mi][2], afrag[z][mi][3],
                            cvta_s(&Asl[z * G1_AS_Z + row * AS_STRIDE + col]));
                }
                #pragma unroll
                for (int np = 0; np < 4; np++) {
                    int kr = ks + (lane & 15);
                    int nc = wn * 64 + np * 16 + (lane >> 4) * 8;
                    ldsm_x4t(bfrag[z][2*np][0], bfrag[z][2*np][1],
                             bfrag[z][2*np+1][0], bfrag[z][2*np+1][1],
                             cvta_s(&Bs[z * G1_BS_Z + kr * BS_STRIDE + nc]));
                }
            }
            #pragma unroll
            for (int mi = 0; mi < 3; mi++)
                #pragma unroll
                for (int ni = 0; ni < 8; ni++) {
                    mma16816(acc[mi][ni], afrag[0][mi], bfrag[0][ni]);
                    mma16816(acc[mi][ni], afrag[0][mi], bfrag[1][ni]);
                    mma16816(acc[mi][ni], afrag[1][mi], bfrag[0][ni]);
                }
        }
        __syncthreads();
    }

    #pragma unroll
    for (int mi = 0; mi < 3; mi++)
        #pragma unroll
        for (int ni = 0; ni < 8; ni++) {
            int row = m0 + wm * 48 + mi * 16 + (lane >> 2);
            int col = n0 + wn * 64 + ni * 8 + 2 * (lane & 3);
            *(float2*)&Cc[(size_t)row * HW + col]       = *(float2*)&acc[mi][ni][0];
            *(float2*)&Cc[(size_t)(row + 8) * HW + col] = *(float2*)&acc[mi][ni][2];
        }
}

// ===================== GEMM2: pure bf16 hi/lo, 3-stage =====================
#define AS_Z   (GBM * AS_STRIDE)
#define AS_ST  (2 * AS_Z)
#define BS_Z   (GBK * BS_STRIDE)
#define BS_ST  (2 * BS_Z)
#define BS_BASE (3 * AS_ST)
#define GSMEM_BYTES ((BS_BASE + 3 * BS_ST) * 2)

__global__ __launch_bounds__(256) void gemm_bf16_pipe(
    const __nv_bfloat16* __restrict__ Ahi, const __nv_bfloat16* __restrict__ Alo, size_t aBatch,
    const __nv_bfloat16* __restrict__ Xhi, const __nv_bfloat16* __restrict__ Xlo, size_t xBatch,
    float* __restrict__ Cc, size_t cBatch)
{
    extern __shared__ __nv_bfloat16 smem[];
    const int b = blockIdx.z;
    Ahi += (size_t)b * aBatch;  Alo += (size_t)b * aBatch;
    Xhi += (size_t)b * xBatch;  Xlo += (size_t)b * xBatch;
    Cc  += (size_t)b * cBatch;

    const int n0 = blockIdx.x * GBN;
    const int m0 = blockIdx.y * GBM;

    const int t    = threadIdx.x;
    const int lane = t & 31;
    const int w    = t >> 5;
    const int wm   = w & 3;
    const int wn   = w >> 2;

    float acc[3][8][4];
    #pragma unroll
    for (int mi = 0; mi < 3; mi++)
        #pragma unroll
        for (int ni = 0; ni < 8; ni++)
            #pragma unroll
            for (int r = 0; r < 4; r++) acc[mi][ni][r] = 0.f;

    auto loadStage = [&](int st, int k0) {
        #pragma unroll
        for (int i = 0; i < 3; i++) {
            int e   = t + i * 256;
            int row = e >> 2;
            int kq  = (e & 3) * 8;
            const size_t gsrc = (size_t)(m0 + row) * 192 + k0 + kq;
            cp16(cvta_s(&smem[st * AS_ST + 0 * AS_Z + row * AS_STRIDE + kq]), &Ahi[gsrc]);
            cp16(cvta_s(&smem[st * AS_ST + 1 * AS_Z + row * AS_STRIDE + kq]), &Alo[gsrc]);
        }
        #pragma unroll
        for (int i = 0; i < 2; i++) {
            int e  = t + i * 256;
            int kr = e >> 4;
            int nc = (e & 15) * 8;
            const size_t gsrc = (size_t)(k0 + kr) * HW + n0 + nc;
            cp16(cvta_s(&smem[BS_BASE + st * BS_ST + 0 * BS_Z + kr * BS_STRIDE + nc]), &Xhi[gsrc]);
            cp16(cvta_s(&smem[BS_BASE + st * BS_ST + 1 * BS_Z + kr * BS_STRIDE + nc]), &Xlo[gsrc]);
        }
    };

    loadStage(0, 0);
    asm volatile("cp.async.commit_group;");
    loadStage(1, GBK);
    asm volatile("cp.async.commit_group;");

    #pragma unroll
    for (int it = 0; it < 6; it++) {
        const int st = it % 3;
        if (it < 4) {
            loadStage((it + 2) % 3, (it + 2) * GBK);
            asm volatile("cp.async.commit_group;");
            asm volatile("cp.async.wait_group 2;");
        } else if (it == 4) {
            asm volatile("cp.async.wait_group 1;");
        } else {
            asm volatile("cp.async.wait_group 0;");
        }
        __syncthreads();

        const __nv_bfloat16* As = &smem[st * AS_ST];
        const __nv_bfloat16* Bs = &smem[BS_BASE + st * BS_ST];

        #pragma unroll
        for (int ks = 0; ks < GBK; ks += 16) {
            uint32_t afrag[2][3][4];
            uint32_t bfrag[2][8][2];
            #pragma unroll
            for (int z = 0; z < 2; z++) {
                #pragma unroll
                for (int mi = 0; mi < 3; mi++) {
                    int row = wm * 48 + mi * 16 + (lane & 15);
                    int col = ks + (lane >> 4) * 8;
                    ldsm_x4(afrag[z][mi][0], afrag[z][mi][1], afrag[z][mi][2], afrag[z][mi][3],
                            cvta_s(&As[z * AS_Z + row * AS_STRIDE + col]));
                }
                #pragma unroll
                for (int np = 0; np < 4; np++) {
                    int kr = ks + (lane & 15);
                    int nc = wn * 64 + np * 16 + (lane >> 4) * 8;
                    ldsm_x4t(bfrag[z][2*np][0], bfrag[z][2*np][1],
                             bfrag[z][2*np+1][0], bfrag[z][2*np+1][1],
                             cvta_s(&Bs[z * BS_Z + kr * BS_STRIDE + nc]));
                }
            }
            #pragma unroll
            for (int mi = 0; mi < 3; mi++)
                #pragma unroll
                for (int ni = 0; ni < 8; ni++) {
                    mma16816(acc[mi][ni], afrag[0][mi], bfrag[0][ni]);
                    mma16816(acc[mi][ni], afrag[0][mi], bfrag[1][ni]);
                    mma16816(acc[mi][ni], afrag[1][mi], bfrag[0][ni]);
                }
        }
        __syncthreads();
    }

    #pragma unroll
    for (int mi = 0; mi < 3; mi++)
        #pragma unroll
        for (int ni = 0; ni < 8; ni++) {
            int row = m0 + wm * 48 + mi * 16 + (lane >> 2);
            int col = n0 + wn * 64 + ni * 8 + 2 * (lane & 3);
            *(float2*)&Cc[(size_t)row * HW + col]       = *(float2*)&acc[mi][ni][0];
            *(float2*)&Cc[(size_t)(row + 8) * HW + col] = *(float2*)&acc[mi][ni][2];
        }
}

// ---------------- tiled depthwise 3x3 conv + fused sumsq (4 cols/thread) -------
__global__ __launch_bounds__(256) void k_dwconv(const float* __restrict__ w)
{
    const int ch = blockIdx.y;
    const int b  = blockIdx.z;
    const int y0 = blockIdx.x * DW_ROWS;
    const int t  = threadIdx.x;
    const int tx = t & 63;
    const int ty = t >> 6;

    __shared__ float tile[DW_ROWS + 2][264];

    const float w0 = __ldg(&w[ch * 9 + 0]), w1 = __ldg(&w[ch * 9 + 1]), w2 = __ldg(&w[ch * 9 + 2]);
    const float w3 = __ldg(&w[ch * 9 + 3]), w4 = __ldg(&w[ch * 9 + 4]), w5 = __ldg(&w[ch * 9 + 5]);
    const float w6 = __ldg(&w[ch * 9 + 6]), w7 = __ldg(&w[ch * 9 + 7]), w8 = __ldg(&w[ch * 9 + 8]);

    const float* src = g_qkv + ((size_t)b * C3 + ch) * HW;

    for (int i = t; i < (DW_ROWS + 2) * 64; i += 256) {
        int r = i >> 6;
        int j = i & 63;
        int y = y0 + r - 1;
        float4 v = make_float4(0.f, 0.f, 0.f, 0.f);
        if (y >= 0 && y < IMG) v = *(const float4*)&src[y * IMG + j * 4];
        *(float4*)&tile[r][4 + 4 * j] = v;
    }
    if (t < DW_ROWS + 2) { tile[t][3] = 0.f; tile[t][260] = 0.f; }
    __syncthreads();

    __nv_bfloat16* hi = g_dw_hi + ((size_t)b * C3 + ch) * HW;
    __nv_bfloat16* lo = g_dw_lo + ((size_t)b * C3 + ch) * HW;

    float r0[6], r1[6], r2[6];
    const int cb = 4 * tx;
    #define LOADROW(dst, R) do {                               \
        float4 mq = *(const float4*)&tile[(R)][4 + cb];        \
        dst[0] = tile[(R)][3 + cb];                            \
        dst[1] = mq.x; dst[2] = mq.y; dst[3] = mq.z; dst[4] = mq.w; \
        dst[5] = tile[(R)][8 + cb];                            \
    } while (0)

    LOADROW(r0, ty * 8 + 0);
    LOADROW(r1, ty * 8 + 1);

    float ssq = 0.f;
    #pragma unroll
    for (int r = 0; r < 8; r++) {
        LOADROW(r2, ty * 8 + r + 2);
        float s[4];
        BF4 hh, ll;
        #pragma unroll
        for (int c = 0; c < 4; c++) {
            s[c] = w0 * r0[c] + w1 * r0[c + 1] + w2 * r0[c + 2]
                 + w3 * r1[c] + w4 * r1[c + 1] + w5 * r1[c + 2]
                 + w6 * r2[c] + w7 * r2[c + 1] + w8 * r2[c + 2];
            hh.h[c] = __float2bfloat16_rn(s[c]);
            ll.h[c] = __float2bfloat16_rn(s[c] - __bfloat162float(hh.h[c]));
            ssq += s[c] * s[c];
        }
        const int p = (y0 + ty * 8 + r) * IMG + cb;
        *(uint2*)&hi[p] = hh.u;
        *(uint2*)&lo[p] = ll.u;
        #pragma unroll
        for (int c = 0; c < 6; c++) { r0[c] = r1[c]; r1[c] = r2[c]; }
    }
    #undef LOADROW

    if (ch < 2 * C) {
        #pragma unroll
        for (int st = 16; st > 0; st >>= 1)
            ssq += __shfl_xor_sync(0xffffffffu, ssq, st);
        __shared__ float wred[8];
        if ((t & 31) == 0) wred[t >> 5] = ssq;
        __syncthreads();
        if (t == 0) {
            float s = 0.f;
            #pragma unroll
            for (int i = 0; i < 8; i++) s += wred[i];
            g_ssq_part[((size_t)b * 2 * C + ch) * (IMG / DW_ROWS) + blockIdx.x] = s;
        }
    }
}

// ---------------- Gram via HMMA, cp.async double-buffered ----------------
// Grid (64, NH, B), 128 threads = 4 warps, each warp a 16-px quarter of a 64-px
// tile; 1024-px chunks, 16 tiles per chunk, double-buffered loads.
// smem per stage: [qk(2)][z(2)][48 rows][72 cols bf16] = 27648B; 2 stages = 55296B.
#define GR_ROW   72
#define GR_QK    (48 * GR_ROW)        // elems per (stage,qk,z) slab? actually per z
#define GR_STAGE (2 * 2 * 48 * GR_ROW) // 13824 elems
#define GR_SMEM  (2 * GR_STAGE * 2)   // bytes = 55296

__global__ __launch_bounds__(128) void k_gram_mma()
{
    extern __shared__ __nv_bfloat16 gsm[];
    const int chunk = blockIdx.x;   // 64 chunks of 1024 px
    const int h     = blockIdx.y;
    const int b     = blockIdx.z;

    const size_t qoff = ((size_t)b * C3 + h * CPH) * HW + (size_t)chunk * 1024;
    const __nv_bfloat16* stream[4] = {
        g_dw_hi + qoff,                      // qh
        g_dw_lo + qoff,                      // ql
        g_dw_hi + qoff + (size_t)C * HW,     // kh
        g_dw_lo + qoff + (size_t)C * HW      // kl
    };

    const int t    = threadIdx.x;
    const int lane = t & 31;
    const int w    = t >> 5;
    const int ks   = w * 16;

    float acc[3][6][4];
    #pragma unroll
    for (int mi = 0; mi < 3; mi++)
        #pragma unroll
        for (int ni = 0; ni < 6; ni++)
            #pragma unroll
            for (int r = 0; r < 4; r++) acc[mi][ni][r] = 0.f;

    // jobs: 4 streams x 48 rows x 8 16B-segments = 1536 -> 12 per thread
    auto loadStage = [&](int st, int px0) {
        #pragma unroll
        for (int i = 0; i < 12; i++) {
            int job = t + i * 128;
            int seg = job & 7;
            int row = (job >> 3) % 48;
            int s   = (job >> 3) / 48;
            cp16(cvta_s(&gsm[st * GR_STAGE + s * (48 * GR_ROW) + row * GR_ROW + seg * 8]),
                 &stream[s][(size_t)row * HW + px0 + seg * 8]);
        }
    };

    loadStage(0, 0);
    asm volatile("cp.async.commit_group;");

    for (int it = 0; it < 16; it++) {
        const int st = it & 1;
        if (it < 15) {
            loadStage(st ^ 1, (it + 1) * 64);
            asm volatile("cp.async.commit_group;");
            asm volatile("cp.async.wait_group 1;");
        } else {
            asm volatile("cp.async.wait_group 0;");
        }
        __syncthreads();

        // stream index: 0=qh,1=ql,2=kh,3=kl ; Q slab at s=0/1, K slab at s=2/3
        const __nv_bfloat16* Qz[2] = { &gsm[st * GR_STAGE + 0 * (48 * GR_ROW)],
                                       &gsm[st * GR_STAGE + 1 * (48 * GR_ROW)] };
        const __nv_bfloat16* Kz[2] = { &gsm[st * GR_STAGE + 2 * (48 * GR_ROW)],
                                       &gsm[st * GR_STAGE + 3 * (48 * GR_ROW)] };

        uint32_t afrag[2][3][4], bfrag[2][3][4];
        #pragma unroll
        for (int z = 0; z < 2; z++) {
            #pragma unroll
            for (int mi = 0; mi < 3; mi++)
                ldsm_x4(afrag[z][mi][0], afrag[z][mi][1], afrag[z][mi][2], afrag[z][mi][3],
                        cvta_s(&Qz[z][(mi * 16 + (lane & 15)) * GR_ROW + ks + (lane >> 4) * 8]));
            #pragma unroll
            for (int np = 0; np < 3; np++)
                ldsm_x4(bfrag[z][np][0], bfrag[z][np][1], bfrag[z][np][2], bfrag[z][np][3],
                        cvta_s(&Kz[z][(np * 16 + (lane & 15)) * GR_ROW + ks + (lane >> 4) * 8]));
        }
        // B frag pairing from non-trans x4 over [n16][k16]: n-lo={r0,r2}, n-hi={r1,r3}
        #pragma unroll
        for (int mi = 0; mi < 3; mi++)
            #pragma unroll
            for (int np = 0; np < 3; np++) {
                mma16816_2(acc[mi][2*np],   afrag[0][mi], bfrag[0][np][0], bfrag[0][np][2]);
                mma16816_2(acc[mi][2*np],   afrag[0][mi], bfrag[1][np][0], bfrag[1][np][2]);
                mma16816_2(acc[mi][2*np],   afrag[1][mi], bfrag[0][np][0], bfrag[0][np][2]);
                mma16816_2(acc[mi][2*np+1], afrag[0][mi], bfrag[0][np][1], bfrag[0][np][3]);
                mma16816_2(acc[mi][2*np+1], afrag[0][mi], bfrag[1][np][1], bfrag[1][np][3]);
                mma16816_2(acc[mi][2*np+1], afrag[1][mi], bfrag[0][np][1], bfrag[0][np][3]);
            }
        __syncthreads();
    }

    const size_t base = (((size_t)(b * NH + h)) * 256 + chunk * 4 + w) * (CPH * CPH);
    #pragma unroll
    for (int mi = 0; mi < 3; mi++)
        #pragma unroll
        for (int ni = 0; ni < 6; ni++) {
            int row = mi * 16 + (lane >> 2);
            int col = ni * 8 + 2 * (lane & 3);
            *(float2*)&g_gram_part[base + (size_t)row * CPH + col]       = *(float2*)&acc[mi][ni][0];
            *(float2*)&g_gram_part[base + (size_t)(row + 8) * CPH + col] = *(float2*)&acc[mi][ni][2];
        }
}

__global__ void k_gram_reduce()
{
    const int idx = blockIdx.x * blockDim.x + threadIdx.x;
    if (idx >= B * NH * CPH * CPH) return;
    const int bh = idx / (CPH * CPH);
    const int cd = idx % (CPH * CPH);
    float s = 0.f;
    for (int ck = 0; ck < 256; ck++)
        s += g_gram_part[((size_t)bh * 256 + ck) * (CPH * CPH) + cd];
    g_gram[idx] = s;
}

// ---------------- softmax (with fused sumsq finalize) ----------------
__global__ void k_softmax(const float* __restrict__ temperature)
{
    const int bh = blockIdx.x;
    const int b  = bh >> 2;
    const int h  = bh & 3;
    const int c  = threadIdx.x;

    __shared__ float snq[CPH], snk[CPH];
    if (c < CPH) {
        float sq = 0.f, sk = 0.f;
        const size_t qb = ((size_t)b * 2 * C + 0 * C + h * CPH + c) * (IMG / DW_ROWS);
        const size_t kb = ((size_t)b * 2 * C + 1 * C + h * CPH + c) * (IMG / DW_ROWS);
        #pragma unroll
        for (int i = 0; i < IMG / DW_ROWS; i++) {
            sq += g_ssq_part[qb + i];
            sk += g_ssq_part[kb + i];
        }
        snq[c] = fmaxf(sqrtf(sq), 1e-12f);
        snk[c] = fmaxf(sqrtf(sk), 1e-12f);
    }
    __syncthreads();
    if (c >= CPH) return;

    const float tv = temperature[h];
    const float nq = snq[c];

    float vals[CPH];
    float mx = -1e30f;
    #pragma unroll 4
    for (int d = 0; d < CPH; d++) {
        float v = g_gram[bh * (CPH * CPH) + c * CPH + d] / (nq * snk[d]) * tv;
        vals[d] = v;
        mx = fmaxf(mx, v);
    }
    float sum = 0.f;
    #pragma unroll 4
    for (int d = 0; d < CPH; d++) {
        vals[d] = expf(vals[d] - mx);
        sum += vals[d];
    }
    const float inv = 1.f / sum;
    #pragma unroll 4
    for (int d = 0; d < CPH; d++)
        g_attn[bh * (CPH * CPH) + c * CPH + d] = vals[d] * inv;
}

// ---------------- M = proj @ blockdiag(attn), fused hi/lo split ----------------
__global__ void k_mixW(const float* __restrict__ proj_w)
{
    const int o  = blockIdx.x;
    const int b  = blockIdx.y;
    const int dg = threadIdx.x;
    const int h  = dg / CPH;
    const int d  = dg % CPH;
    float s = 0.f;
    #pragma unroll 8
    for (int cl = 0; cl < CPH; cl++)
        s += proj_w[o * C + h * CPH + cl] *
             g_attn[((size_t)(b * NH + h)) * (CPH * CPH) + cl * CPH + d];
    __nv_bfloat16 hh = __float2bfloat16_rn(s);
    g_M_hi[((size_t)b * C + o) * C + dg] = hh;
    g_M_lo[((size_t)b * C + o) * C + dg] = __float2bfloat16_rn(s - __bfloat162float(hh));
}

// ---------------- launch ----------------
extern "C" void kernel_launch(void* const* d_in, const int* in_sizes, int n_in,
                              void* d_out, int out_size)
{
    const float* x      = (const float*)d_in[0];
    const float* qkv_w  = (const float*)d_in[1];
    const float* dw_w   = (const float*)d_in[2];
    const float* proj_w = (const float*)d_in[3];
    const float* temp   = (const float*)d_in[4];
    float* out = (float*)d_out;

    float* p_qkv;
    __nv_bfloat16 *p_wh, *p_wl, *p_dh, *p_dl, *p_Mh, *p_Ml;
    cudaGetSymbolAddress((void**)&p_qkv, g_qkv);
    cudaGetSymbolAddress((void**)&p_wh,  g_w_hi);
    cudaGetSymbolAddress((void**)&p_wl,  g_w_lo);
    cudaGetSymbolAddress((void**)&p_dh,  g_dw_hi);
    cudaGetSymbolAddress((void**)&p_dl,  g_dw_lo);
    cudaGetSymbolAddress((void**)&p_Mh,  g_M_hi);
    cudaGetSymbolAddress((void**)&p_Ml,  g_M_lo);

    cudaFuncSetAttribute(gemm1_fused,    cudaFuncAttributeMaxDynamicSharedMemorySize, G1_SMEM);
    cudaFuncSetAttribute(gemm_bf16_pipe, cudaFuncAttributeMaxDynamicSharedMemorySize, GSMEM_BYTES);
    cudaFuncSetAttribute(k_gram_mma,     cudaFuncAttributeMaxDynamicSharedMemorySize, GR_SMEM);

    // 0) split weights to bf16 hi/lo (tiny)
    {
        int w4 = C3 * C / 4;
        k_cvt<<<(w4 + 255) / 256, 256>>>(qkv_w, p_wh, p_wl, w4);
    }

    // 1) qkv = W @ x
    gemm1_fused<<<dim3(HW / GBN, C3 / GBM, B), 256, G1_SMEM>>>(p_wh, p_wl, x, p_qkv);

    // 2) depthwise conv + sumsq partials
    k_dwconv<<<dim3(IMG / DW_ROWS, C3, B), 256>>>(dw_w);

    // 3) Gram (HMMA, cp.async pipelined) + reduce
    k_gram_mma<<<dim3(64, NH, B), 128, GR_SMEM>>>();
    k_gram_reduce<<<(B * NH * CPH * CPH + 255) / 256, 256>>>();

    // 4) softmax (sumsq fused), fold proj into M (hi/lo fused)
    k_softmax<<<B * NH, 64>>>(temp);
    k_mixW<<<dim3(C, B), C>>>(proj_w);

    // 5) out = M @ v
    gemm_bf16_pipe<<<dim3(HW / GBN, C / GBM, B), 256, GSMEM_BYTES>>>(
        p_Mh, p_Ml, (size_t)C * C,
        p_dh + (size_t)2 * C * HW, p_dl + (size_t)2 * C * HW, (size_t)C3 * HW,
        out, (size_t)C * HW);
}